// round 1
// baseline (speedup 1.0000x reference)
#include <cuda_runtime.h>
#include <cstdint>

// Problem constants
#define NB   64
#define NT   1000
#define NN   512      // OUT
#define NI   512      // IN
#define NM   (NB*NT)  // 64000 rows of the input GEMM

// zs size and states base in d_out
#define ZS_ELEMS   (NB*NT*NN)            // 32,768,000
#define ST_STRIDE  ((NT+1)*NN)           // per (s,b) slab: 512,512
// states index: ZS_ELEMS + ((s*NB + b)*(NT+1) + t)*NN + o

// Scratch (device globals — no allocation allowed)
__device__ float g_cur[(size_t)NM * NN];   // cur_in, row-major (b*T+t, o)
__device__ float g_Rt[NN * NN];            // R transposed: Rt[j][o] = R[o][j]

// ---------------------------------------------------------------------------
// R transpose (so active column j of the recurrent matvec is contiguous)
// ---------------------------------------------------------------------------
__global__ void transpose_R(const float* __restrict__ R) {
    __shared__ float tile[32][33];
    int bx = blockIdx.x * 32;  // j block
    int by = blockIdx.y * 32;  // o block
    int x = bx + threadIdx.x;  // j
    int y = by + threadIdx.y;  // o
    tile[threadIdx.y][threadIdx.x] = R[y * NN + x];
    __syncthreads();
    // Rt[j][o] = R[o][j]
    g_Rt[(bx + threadIdx.y) * NN + (by + threadIdx.x)] = tile[threadIdx.x][threadIdx.y];
}

// ---------------------------------------------------------------------------
// SGEMM: g_cur[m][n] = sum_k X[m][k] * W[n][k] + bias[n]
// BM=BN=128, BK=32, 256 threads, 8x8 per thread
// ---------------------------------------------------------------------------
__global__ __launch_bounds__(256) void gemm_kernel(const float* __restrict__ X,
                                                   const float* __restrict__ W,
                                                   const float* __restrict__ bias) {
    __shared__ float As[32][129];
    __shared__ float Bs[32][129];

    int tid = threadIdx.x;
    int block_m = blockIdx.x * 128;
    int block_n = blockIdx.y * 128;

    int tx = tid & 15;   // n direction
    int ty = tid >> 4;   // m direction

    float acc[8][8];
#pragma unroll
    for (int i = 0; i < 8; i++)
#pragma unroll
        for (int j = 0; j < 8; j++) acc[i][j] = 0.f;

    int lr = tid >> 3;        // 0..31  (row within 32-row chunk)
    int lc = (tid & 7) * 4;   // 0,4,...,28 (k offset, float4)

    for (int kt = 0; kt < NI; kt += 32) {
#pragma unroll
        for (int i = 0; i < 4; i++) {
            int r = lr + 32 * i;
            float4 a = *(const float4*)(X + (size_t)(block_m + r) * NI + kt + lc);
            As[lc + 0][r] = a.x; As[lc + 1][r] = a.y;
            As[lc + 2][r] = a.z; As[lc + 3][r] = a.w;
            float4 bv = *(const float4*)(W + (size_t)(block_n + r) * NI + kt + lc);
            Bs[lc + 0][r] = bv.x; Bs[lc + 1][r] = bv.y;
            Bs[lc + 2][r] = bv.z; Bs[lc + 3][r] = bv.w;
        }
        __syncthreads();

#pragma unroll
        for (int k = 0; k < 32; k++) {
            float ra[8], rb[8];
#pragma unroll
            for (int i = 0; i < 8; i++) ra[i] = As[k][ty * 8 + i];
#pragma unroll
            for (int j = 0; j < 8; j++) rb[j] = Bs[k][tx * 8 + j];
#pragma unroll
            for (int i = 0; i < 8; i++)
#pragma unroll
                for (int j = 0; j < 8; j++) acc[i][j] = fmaf(ra[i], rb[j], acc[i][j]);
        }
        __syncthreads();
    }

    // epilogue: + bias, write float4
#pragma unroll
    for (int i = 0; i < 8; i++) {
        int row = block_m + ty * 8 + i;
#pragma unroll
        for (int j = 0; j < 8; j += 4) {
            int col = block_n + tx * 8 + j;
            float4 v;
            v.x = acc[i][j + 0] + bias[col + 0];
            v.y = acc[i][j + 1] + bias[col + 1];
            v.z = acc[i][j + 2] + bias[col + 2];
            v.w = acc[i][j + 3] + bias[col + 3];
            *(float4*)(g_cur + (size_t)row * NN + col) = v;
        }
    }
}

// ---------------------------------------------------------------------------
// ALIF scan: 1 CTA per batch, 512 threads = 1 neuron each.
// Per step: sparse recurrent gather (active spike columns of Rt from L2),
// elementwise state update, ballot-based active-list compaction.
// ---------------------------------------------------------------------------
__global__ __launch_bounds__(512) void alif_scan(const float* __restrict__ beta,
                                                 const float* __restrict__ beta2,
                                                 const float* __restrict__ decay_v,
                                                 const float* __restrict__ decay_b,
                                                 float* __restrict__ out) {
    const int b = blockIdx.x;
    const int o = threadIdx.x;
    const int w = o >> 5;
    const int lane = o & 31;

    __shared__ uint32_t zmask[16];
    __shared__ int act[NN];

    const float dv = decay_v[o];
    const float db = decay_b[o];
    const float be = beta[o];
    const float b2 = beta2[o];
    const float omdv = 1.f - dv;
    const float omdb = 1.f - db;

    float v = 0.f, bb = 0.f, zprev = 0.f;
    int nact = 0;

    const float* curb = g_cur + ((size_t)b * NT) * NN + o;
    const float* Rto  = g_Rt + o;

    float* zs = out;
    float* vf = out + ZS_ELEMS + ((size_t)(0 * NB + b)) * ST_STRIDE + o;
    float* zf = out + ZS_ELEMS + ((size_t)(1 * NB + b)) * ST_STRIDE + o;
    float* bf = out + ZS_ELEMS + ((size_t)(2 * NB + b)) * ST_STRIDE + o;

    // t=0 pads in states
    vf[0] = 0.f; zf[0] = 0.f; bf[0] = 0.f;

    for (int t = 0; t < NT; t++) {
        __syncthreads();  // act[] (written at end of previous iter) visible

        float c = curb[(size_t)t * NN];  // issue early; DRAM stream

        // sparse recurrent gather: rec[o] = sum_{j active} Rt[j][o]
        float rec = 0.f;
        int k = 0;
        for (; k + 8 <= nact; k += 8) {
            int j0 = act[k + 0], j1 = act[k + 1], j2 = act[k + 2], j3 = act[k + 3];
            int j4 = act[k + 4], j5 = act[k + 5], j6 = act[k + 6], j7 = act[k + 7];
            float r0 = Rto[j0 * NN], r1 = Rto[j1 * NN], r2 = Rto[j2 * NN], r3 = Rto[j3 * NN];
            float r4 = Rto[j4 * NN], r5 = Rto[j5 * NN], r6 = Rto[j6 * NN], r7 = Rto[j7 * NN];
            rec += ((r0 + r1) + (r2 + r3)) + ((r4 + r5) + (r6 + r7));
        }
        for (; k < nact; k++) rec += Rto[act[k] * NN];

        // state update
        v *= (1.f - zprev);
        float v_t = dv * v + omdv * ((c + rec) - bb);
        float z_t = (v_t >= 1.0f) ? 1.f : 0.f;
        float b_t = db * bb + omdb * (be * v_t + b2 * z_t);

        // outputs
        int tpo = (t + 1) * NN;
        zs[((size_t)b * NT + t) * NN + o] = z_t;
        vf[tpo] = v_t;
        zf[tpo] = z_t;
        bf[tpo] = b_t;

        // build active list for next step
        uint32_t m = __ballot_sync(0xffffffffu, z_t != 0.f);
        if (lane == 0) zmask[w] = m;
        __syncthreads();

        int myoff = 0, tot = 0;
#pragma unroll
        for (int i = 0; i < 16; i++) {
            int p = __popc(zmask[i]);
            if (i < w) myoff += p;
            tot += p;
        }
        if (z_t != 0.f) {
            int rank = __popc(m & ((1u << lane) - 1u));
            act[myoff + rank] = o;
        }
        nact = tot;

        v = v_t; bb = b_t; zprev = z_t;
    }
}

// ---------------------------------------------------------------------------
extern "C" void kernel_launch(void* const* d_in, const int* in_sizes, int n_in,
                              void* d_out, int out_size) {
    const float* x     = (const float*)d_in[0];  // (B,T,IN)
    const float* W     = (const float*)d_in[1];  // (OUT,IN)
    const float* bias  = (const float*)d_in[2];  // (OUT,)
    const float* R     = (const float*)d_in[3];  // (OUT,OUT)
    const float* beta  = (const float*)d_in[4];
    const float* beta2 = (const float*)d_in[5];
    const float* dv    = (const float*)d_in[6];
    const float* db    = (const float*)d_in[7];
    float* out = (float*)d_out;

    dim3 tgrid(NN / 32, NN / 32), tblk(32, 32);
    transpose_R<<<tgrid, tblk>>>(R);

    dim3 ggrid(NM / 128, NN / 128);
    gemm_kernel<<<ggrid, 256>>>(x, W, bias);

    alif_scan<<<NB, NN>>>(beta, beta2, dv, db, out);
}

// round 3
// speedup vs baseline: 1.4743x; 1.4743x over previous
#include <cuda_runtime.h>
#include <cuda_bf16.h>
#include <cstdint>

// Problem constants
#define NB   64
#define NT   1000
#define NN   512
#define NI   512
#define NM   (NB*NT)

#define ZS_ELEMS   (NB*NT*NN)
#define ST_STRIDE  ((NT+1)*NN)

// ---------------------------------------------------------------------------
// Scratch (device globals — no allocation allowed)
// ---------------------------------------------------------------------------
__device__ float         g_cur[(size_t)NM * NN];
__device__ float         g_Rt[NN * NN];
__device__ __nv_bfloat16 g_xhi[(size_t)NM * NI];
__device__ __nv_bfloat16 g_xlo[(size_t)NM * NI];
__device__ __nv_bfloat16 g_whi[NN * NI];
__device__ __nv_bfloat16 g_wlo[NN * NI];

// ---------------------------------------------------------------------------
// Portable PTX helpers (sm_80+ features only — NO tcgen05 on this build)
// ---------------------------------------------------------------------------
__device__ __forceinline__ uint32_t smem_to_u32(const void* p) {
    uint32_t a;
    asm("{ .reg .u64 t; cvta.to.shared.u64 t, %1; cvt.u32.u64 %0, t; }" : "=r"(a) : "l"(p));
    return a;
}
__device__ __forceinline__ void cp_async16(uint32_t dst, const void* src) {
    asm volatile("cp.async.cg.shared.global [%0], [%1], 16;" :: "r"(dst), "l"(src) : "memory");
}
__device__ __forceinline__ void ldsm_x4(uint32_t r[4], uint32_t addr) {
    asm volatile("ldmatrix.sync.aligned.m8n8.x4.shared.b16 {%0,%1,%2,%3}, [%4];"
        : "=r"(r[0]), "=r"(r[1]), "=r"(r[2]), "=r"(r[3]) : "r"(addr));
}
__device__ __forceinline__ void mma16816(float d[4], const uint32_t a[4], const uint32_t b[2]) {
    asm volatile("mma.sync.aligned.m16n8k16.row.col.f32.bf16.bf16.f32 "
        "{%0,%1,%2,%3}, {%4,%5,%6,%7}, {%8,%9}, {%0,%1,%2,%3};"
        : "+f"(d[0]), "+f"(d[1]), "+f"(d[2]), "+f"(d[3])
        : "r"(a[0]), "r"(a[1]), "r"(a[2]), "r"(a[3]), "r"(b[0]), "r"(b[1]));
}
#define SWZ(off) ((off) ^ (((off) >> 3) & 0x70))

// ---------------------------------------------------------------------------
// R transpose
// ---------------------------------------------------------------------------
__global__ void transpose_R(const float* __restrict__ R) {
    __shared__ float tile[32][33];
    int bx = blockIdx.x * 32, by = blockIdx.y * 32;
    tile[threadIdx.y][threadIdx.x] = R[(by + threadIdx.y) * NN + bx + threadIdx.x];
    __syncthreads();
    g_Rt[(bx + threadIdx.y) * NN + (by + threadIdx.x)] = tile[threadIdx.x][threadIdx.y];
}

// ---------------------------------------------------------------------------
// fp32 -> bf16 hi + bf16 lo splits (write device symbols directly)
// ---------------------------------------------------------------------------
__device__ __forceinline__ void split4(float4 v, ushort4& hv, ushort4& lv) {
    __nv_bfloat16 h0 = __float2bfloat16(v.x), h1 = __float2bfloat16(v.y);
    __nv_bfloat16 h2 = __float2bfloat16(v.z), h3 = __float2bfloat16(v.w);
    hv.x = __bfloat16_as_ushort(h0); hv.y = __bfloat16_as_ushort(h1);
    hv.z = __bfloat16_as_ushort(h2); hv.w = __bfloat16_as_ushort(h3);
    lv.x = __bfloat16_as_ushort(__float2bfloat16(v.x - __bfloat162float(h0)));
    lv.y = __bfloat16_as_ushort(__float2bfloat16(v.y - __bfloat162float(h1)));
    lv.z = __bfloat16_as_ushort(__float2bfloat16(v.z - __bfloat162float(h2)));
    lv.w = __bfloat16_as_ushort(__float2bfloat16(v.w - __bfloat162float(h3)));
}
__global__ __launch_bounds__(256) void convert_x(const float* __restrict__ src) {
    int i = blockIdx.x * 256 + threadIdx.x;
    ushort4 hv, lv;
    split4(((const float4*)src)[i], hv, lv);
    ((ushort4*)g_xhi)[i] = hv;
    ((ushort4*)g_xlo)[i] = lv;
}
__global__ __launch_bounds__(256) void convert_w(const float* __restrict__ src) {
    int i = blockIdx.x * 256 + threadIdx.x;
    ushort4 hv, lv;
    split4(((const float4*)src)[i], hv, lv);
    ((ushort4*)g_whi)[i] = hv;
    ((ushort4*)g_wlo)[i] = lv;
}

// ---------------------------------------------------------------------------
// bf16-split GEMM via mma.sync (portable HMMA path):
//   g_cur[m][n] = sum_k X[m][k]*W[n][k] + bias[n]
// CTA 128x128, 8 warps (2m x 4n), warp tile 64x32, BK=32, double buffer.
// SMEM stage: 256 rows x 128B; row r<128: A row (hi 64B | lo 64B), r>=128: B.
// 3 passes per fragment set: Ah*Bh + Ah*Bl + Al*Bh (fp32 acc).
// ---------------------------------------------------------------------------
#define BK       32
#define NCHUNK   (NI / BK)     // 16
#define STAGE_B  32768
#define GEMM_SMEM (2 * STAGE_B)

__global__ __launch_bounds__(256) void gemm_tc(const float* __restrict__ bias) {
    extern __shared__ char smem[];
    uint32_t sb = smem_to_u32(smem);
    const int tid = threadIdx.x, lane = tid & 31, wid = tid >> 5;
    const int m0 = blockIdx.y * 128, n0 = blockIdx.x * 128;
    const int wm = (wid & 1) * 64;       // warp m offset in tile
    const int wn = (wid >> 1) * 32;      // warp n offset in tile

    float acc[4][4][4];
#pragma unroll
    for (int i = 0; i < 4; i++)
#pragma unroll
        for (int j = 0; j < 4; j++)
#pragma unroll
            for (int k = 0; k < 4; k++) acc[i][j][k] = 0.f;

    // cp.async source: thread t owns smem row t (A rows 0-127, B rows 128-255)
    const __nv_bfloat16* srcHi;
    const __nv_bfloat16* srcLo;
    if (tid < 128) {
        srcHi = g_xhi + (size_t)(m0 + tid) * NI;
        srcLo = g_xlo + (size_t)(m0 + tid) * NI;
    } else {
        srcHi = g_whi + (size_t)(n0 + tid - 128) * NI;
        srcLo = g_wlo + (size_t)(n0 + tid - 128) * NI;
    }

    auto load_chunk = [&](int c, int s) {
        uint32_t base = sb + s * STAGE_B;
        const __nv_bfloat16* ph = srcHi + c * BK;
        const __nv_bfloat16* pl = srcLo + c * BK;
#pragma unroll
        for (int j = 0; j < 4; j++) {
            cp_async16(base + SWZ((uint32_t)(tid * 128 + j * 16)), ph + j * 8);
            cp_async16(base + SWZ((uint32_t)(tid * 128 + 64 + j * 16)), pl + j * 8);
        }
        asm volatile("cp.async.commit_group;" ::: "memory");
    };

    // ldmatrix lane-address components (row, colByte) precomputed
    const int a_row = wm + (lane & 15);                 // + mt*16
    const int a_cb  = (lane >> 4) * 16;                 // + kk*2 (+64 for lo)
    const int b_row = 128 + wn + (lane & 7) + ((lane >> 4) * 8);  // + p*16
    const int b_cb  = ((lane >> 3) & 1) * 16;           // + kk*2 (+64 for lo)

    load_chunk(0, 0);

    for (int c = 0; c < NCHUNK; c++) {
        const int s = c & 1;
        if (c + 1 < NCHUNK) {
            load_chunk(c + 1, (c + 1) & 1);
            asm volatile("cp.async.wait_group 1;" ::: "memory");
        } else {
            asm volatile("cp.async.wait_group 0;" ::: "memory");
        }
        __syncthreads();

        uint32_t base = sb + s * STAGE_B;
#pragma unroll
        for (int kk = 0; kk < BK; kk += 16) {
            uint32_t ah[4][4], al[4][4], bh[4][2], bl[4][2];
#pragma unroll
            for (int mt = 0; mt < 4; mt++) {
                uint32_t off = (uint32_t)((a_row + mt * 16) * 128 + a_cb + kk * 2);
                ldsm_x4(ah[mt], base + SWZ(off));
                ldsm_x4(al[mt], base + SWZ(off + 64));
            }
#pragma unroll
            for (int p = 0; p < 2; p++) {
                uint32_t off = (uint32_t)((b_row + p * 16) * 128 + b_cb + kk * 2);
                uint32_t t4[4];
                ldsm_x4(t4, base + SWZ(off));
                bh[2 * p][0] = t4[0]; bh[2 * p][1] = t4[1];
                bh[2 * p + 1][0] = t4[2]; bh[2 * p + 1][1] = t4[3];
                ldsm_x4(t4, base + SWZ(off + 64));
                bl[2 * p][0] = t4[0]; bl[2 * p][1] = t4[1];
                bl[2 * p + 1][0] = t4[2]; bl[2 * p + 1][1] = t4[3];
            }
#pragma unroll
            for (int mt = 0; mt < 4; mt++)
#pragma unroll
                for (int nt = 0; nt < 4; nt++) {
                    mma16816(acc[mt][nt], ah[mt], bh[nt]);
                    mma16816(acc[mt][nt], ah[mt], bl[nt]);
                    mma16816(acc[mt][nt], al[mt], bh[nt]);
                }
        }
        __syncthreads();
    }

    // Epilogue: acc frag (m16n8): d0,d1 -> (row, col..col+1), d2,d3 -> (row+8)
    const int erow = m0 + wm + (lane >> 2);
    const int ecol0 = n0 + wn + (lane & 3) * 2;
    float2 brg[4];
#pragma unroll
    for (int nt = 0; nt < 4; nt++)
        brg[nt] = *(const float2*)(bias + ecol0 + nt * 8);
#pragma unroll
    for (int mt = 0; mt < 4; mt++) {
        int r0 = erow + mt * 16;
#pragma unroll
        for (int nt = 0; nt < 4; nt++) {
            float2 v0 = {acc[mt][nt][0] + brg[nt].x, acc[mt][nt][1] + brg[nt].y};
            float2 v1 = {acc[mt][nt][2] + brg[nt].x, acc[mt][nt][3] + brg[nt].y};
            *(float2*)(g_cur + (size_t)r0 * NN + ecol0 + nt * 8) = v0;
            *(float2*)(g_cur + (size_t)(r0 + 8) * NN + ecol0 + nt * 8) = v1;
        }
    }
}

// ---------------------------------------------------------------------------
// ALIF scan: 64 CTAs x 128 threads, 4 neurons/thread (float4 streams),
// 8-deep register prefetch, syncthreads_count fast path.
// ---------------------------------------------------------------------------
__global__ __launch_bounds__(128) void alif_scan(const float* __restrict__ beta,
                                                 const float* __restrict__ beta2,
                                                 const float* __restrict__ decay_v,
                                                 const float* __restrict__ decay_b,
                                                 float* __restrict__ out) {
    const int b = blockIdx.x;
    const int tid = threadIdx.x;
    const int w = tid >> 5, lane = tid & 31;

    __shared__ int wsum[4];
    __shared__ int act[NN];

    const float4 be = ((const float4*)beta)[tid];
    const float4 b2 = ((const float4*)beta2)[tid];
    const float4 dv = ((const float4*)decay_v)[tid];
    const float4 db = ((const float4*)decay_b)[tid];
    const float4 omdv = {1.f - dv.x, 1.f - dv.y, 1.f - dv.z, 1.f - dv.w};
    const float4 omdb = {1.f - db.x, 1.f - db.y, 1.f - db.z, 1.f - db.w};

    float4 v  = {0.f, 0.f, 0.f, 0.f};
    float4 bb = {0.f, 0.f, 0.f, 0.f};
    float4 zp = {0.f, 0.f, 0.f, 0.f};
    int nact = 0;

    const float4* cur4 = (const float4*)(g_cur + (size_t)b * NT * NN);
    const float4* Rt4  = (const float4*)g_Rt;

    float* zsb = out + (size_t)b * NT * NN;
    float* vf  = out + ZS_ELEMS + (size_t)(0 * NB + b) * ST_STRIDE;
    float* zf  = out + ZS_ELEMS + (size_t)(1 * NB + b) * ST_STRIDE;
    float* bf  = out + ZS_ELEMS + (size_t)(2 * NB + b) * ST_STRIDE;

    const float4 zero4 = {0.f, 0.f, 0.f, 0.f};
    ((float4*)vf)[tid] = zero4;
    ((float4*)zf)[tid] = zero4;
    ((float4*)bf)[tid] = zero4;

    float4 cpre[8];
#pragma unroll
    for (int i = 0; i < 8; i++) cpre[i] = cur4[(size_t)i * 128 + tid];

    for (int t = 0; t < NT; t++) {
        float4 c = cpre[t & 7];
        int tp = t + 8;
        if (tp < NT) cpre[t & 7] = cur4[(size_t)tp * 128 + tid];

        float4 rec = {0.f, 0.f, 0.f, 0.f};
        for (int k = 0; k < nact; k++) {
            float4 r = Rt4[(size_t)act[k] * 128 + tid];
            rec.x += r.x; rec.y += r.y; rec.z += r.z; rec.w += r.w;
        }

        v.x *= (1.f - zp.x); v.y *= (1.f - zp.y); v.z *= (1.f - zp.z); v.w *= (1.f - zp.w);
        float4 vt;
        vt.x = dv.x * v.x + omdv.x * ((c.x + rec.x) - bb.x);
        vt.y = dv.y * v.y + omdv.y * ((c.y + rec.y) - bb.y);
        vt.z = dv.z * v.z + omdv.z * ((c.z + rec.z) - bb.z);
        vt.w = dv.w * v.w + omdv.w * ((c.w + rec.w) - bb.w);
        float4 zt;
        zt.x = (vt.x >= 1.0f) ? 1.f : 0.f;
        zt.y = (vt.y >= 1.0f) ? 1.f : 0.f;
        zt.z = (vt.z >= 1.0f) ? 1.f : 0.f;
        zt.w = (vt.w >= 1.0f) ? 1.f : 0.f;
        bb.x = db.x * bb.x + omdb.x * (be.x * vt.x + b2.x * zt.x);
        bb.y = db.y * bb.y + omdb.y * (be.y * vt.y + b2.y * zt.y);
        bb.z = db.z * bb.z + omdb.z * (be.z * vt.z + b2.z * zt.z);
        bb.w = db.w * bb.w + omdb.w * (be.w * vt.w + b2.w * zt.w);
        v = vt; zp = zt;

        ((float4*)zsb)[(size_t)t * 128 + tid] = zt;
        size_t tpo = (size_t)(t + 1) * 128 + tid;
        ((float4*)vf)[tpo] = vt;
        ((float4*)zf)[tpo] = zt;
        ((float4*)bf)[tpo] = bb;

        int any = (zt.x != 0.f) | (zt.y != 0.f) | (zt.z != 0.f) | (zt.w != 0.f);
        int flag = __syncthreads_count(any);
        if (flag) {
            int myspk = (zt.x != 0.f) + (zt.y != 0.f) + (zt.z != 0.f) + (zt.w != 0.f);
            int incl = myspk;
#pragma unroll
            for (int d = 1; d < 32; d <<= 1) {
                int n = __shfl_up_sync(0xffffffffu, incl, d);
                if (lane >= d) incl += n;
            }
            if (lane == 31) wsum[w] = incl;
            __syncthreads();
            int basep = 0, tot = 0;
#pragma unroll
            for (int i = 0; i < 4; i++) {
                int sv = wsum[i];
                if (i < w) basep += sv;
                tot += sv;
            }
            int pos = basep + incl - myspk;
            int o0 = tid * 4;
            if (zt.x != 0.f) act[pos++] = o0 + 0;
            if (zt.y != 0.f) act[pos++] = o0 + 1;
            if (zt.z != 0.f) act[pos++] = o0 + 2;
            if (zt.w != 0.f) act[pos++] = o0 + 3;
            __syncthreads();
            nact = tot;
        } else {
            nact = 0;
        }
    }
}

// ---------------------------------------------------------------------------
extern "C" void kernel_launch(void* const* d_in, const int* in_sizes, int n_in,
                              void* d_out, int out_size) {
    const float* x     = (const float*)d_in[0];
    const float* W     = (const float*)d_in[1];
    const float* bias  = (const float*)d_in[2];
    const float* R     = (const float*)d_in[3];
    const float* beta  = (const float*)d_in[4];
    const float* beta2 = (const float*)d_in[5];
    const float* dvp   = (const float*)d_in[6];
    const float* dbp   = (const float*)d_in[7];
    float* out = (float*)d_out;

    cudaFuncSetAttribute(gemm_tc, cudaFuncAttributeMaxDynamicSharedMemorySize, GEMM_SMEM);

    dim3 tgrid(NN / 32, NN / 32), tblk(32, 32);
    transpose_R<<<tgrid, tblk>>>(R);

    convert_x<<<(NM * NI / 4) / 256, 256>>>(x);
    convert_w<<<(NN * NI / 4) / 256, 256>>>(W);

    dim3 ggrid(NN / 128, NM / 128);   // x = n (4), y = m (500): same-m CTAs adjacent
    gemm_tc<<<ggrid, 256, GEMM_SMEM>>>(bias);

    alif_scan<<<NB, 128>>>(beta, beta2, dvp, dbp, out);
}

// round 4
// speedup vs baseline: 1.6736x; 1.1352x over previous
#include <cuda_runtime.h>
#include <cuda_bf16.h>
#include <cstdint>

// Problem constants
#define NB   64
#define NT   1000
#define NN   512
#define NI   512
#define NM   (NB*NT)

#define ZS_ELEMS   (NB*NT*NN)
#define ST_STRIDE  ((NT+1)*NN)

// ---------------------------------------------------------------------------
// Scratch (device globals — no allocation allowed)
// ---------------------------------------------------------------------------
__device__ float         g_cur[(size_t)NM * NN];
__device__ float         g_Rt[NN * NN];
__device__ __nv_bfloat16 g_xhi[(size_t)NM * NI];
__device__ __nv_bfloat16 g_xlo[(size_t)NM * NI];
__device__ __nv_bfloat16 g_whi[NN * NI];
__device__ __nv_bfloat16 g_wlo[NN * NI];

// ---------------------------------------------------------------------------
// Portable PTX helpers (sm_80+ only — tcgen05 unavailable at compute_103)
// ---------------------------------------------------------------------------
__device__ __forceinline__ uint32_t smem_to_u32(const void* p) {
    uint32_t a;
    asm("{ .reg .u64 t; cvta.to.shared.u64 t, %1; cvt.u32.u64 %0, t; }" : "=r"(a) : "l"(p));
    return a;
}
__device__ __forceinline__ void cp_async16(uint32_t dst, const void* src) {
    asm volatile("cp.async.cg.shared.global [%0], [%1], 16;" :: "r"(dst), "l"(src) : "memory");
}
__device__ __forceinline__ void ldsm_x4(uint32_t r[4], uint32_t addr) {
    asm volatile("ldmatrix.sync.aligned.m8n8.x4.shared.b16 {%0,%1,%2,%3}, [%4];"
        : "=r"(r[0]), "=r"(r[1]), "=r"(r[2]), "=r"(r[3]) : "r"(addr));
}
__device__ __forceinline__ void mma16816(float d[4], const uint32_t a[4], const uint32_t b[2]) {
    asm volatile("mma.sync.aligned.m16n8k16.row.col.f32.bf16.bf16.f32 "
        "{%0,%1,%2,%3}, {%4,%5,%6,%7}, {%8,%9}, {%0,%1,%2,%3};"
        : "+f"(d[0]), "+f"(d[1]), "+f"(d[2]), "+f"(d[3])
        : "r"(a[0]), "r"(a[1]), "r"(a[2]), "r"(a[3]), "r"(b[0]), "r"(b[1]));
}
#define SWZ(off) ((off) ^ (((off) >> 3) & 0x70))

// ---------------------------------------------------------------------------
// R transpose
// ---------------------------------------------------------------------------
__global__ void transpose_R(const float* __restrict__ R) {
    __shared__ float tile[32][33];
    int bx = blockIdx.x * 32, by = blockIdx.y * 32;
    tile[threadIdx.y][threadIdx.x] = R[(by + threadIdx.y) * NN + bx + threadIdx.x];
    __syncthreads();
    g_Rt[(bx + threadIdx.y) * NN + (by + threadIdx.x)] = tile[threadIdx.x][threadIdx.y];
}

// ---------------------------------------------------------------------------
// fp32 -> bf16 hi + bf16 lo splits
// ---------------------------------------------------------------------------
__device__ __forceinline__ void split4(float4 v, ushort4& hv, ushort4& lv) {
    __nv_bfloat16 h0 = __float2bfloat16(v.x), h1 = __float2bfloat16(v.y);
    __nv_bfloat16 h2 = __float2bfloat16(v.z), h3 = __float2bfloat16(v.w);
    hv.x = __bfloat16_as_ushort(h0); hv.y = __bfloat16_as_ushort(h1);
    hv.z = __bfloat16_as_ushort(h2); hv.w = __bfloat16_as_ushort(h3);
    lv.x = __bfloat16_as_ushort(__float2bfloat16(v.x - __bfloat162float(h0)));
    lv.y = __bfloat16_as_ushort(__float2bfloat16(v.y - __bfloat162float(h1)));
    lv.z = __bfloat16_as_ushort(__float2bfloat16(v.z - __bfloat162float(h2)));
    lv.w = __bfloat16_as_ushort(__float2bfloat16(v.w - __bfloat162float(h3)));
}
__global__ __launch_bounds__(256) void convert_x(const float* __restrict__ src) {
    int i = blockIdx.x * 256 + threadIdx.x;
    ushort4 hv, lv;
    split4(((const float4*)src)[i], hv, lv);
    ((ushort4*)g_xhi)[i] = hv;
    ((ushort4*)g_xlo)[i] = lv;
}
__global__ __launch_bounds__(256) void convert_w(const float* __restrict__ src) {
    int i = blockIdx.x * 256 + threadIdx.x;
    ushort4 hv, lv;
    split4(((const float4*)src)[i], hv, lv);
    ((ushort4*)g_whi)[i] = hv;
    ((ushort4*)g_wlo)[i] = lv;
}

// ---------------------------------------------------------------------------
// bf16-split GEMM via mma.sync, 4-stage cp.async pipeline.
//   g_cur[m][n] = sum_k X[m][k]*W[n][k] + bias[n]
// CTA 128x128, 8 warps (2m x 4n), warp tile 64x32, BK=32.
// SMEM stage (32KB): 256 rows x 128B; r<128: A row (hi 64B | lo 64B), r>=128: B.
// 3 passes: Ah*Bh + Ah*Bl + Al*Bh, fp32 acc.
// ---------------------------------------------------------------------------
#define BK       32
#define NCHUNK   (NI / BK)       // 16
#define NSTAGE   4
#define STAGE_B  32768
#define GEMM_SMEM (NSTAGE * STAGE_B)   // 131072

__global__ __launch_bounds__(256) void gemm_tc(const float* __restrict__ bias) {
    extern __shared__ char smem[];
    uint32_t sb = smem_to_u32(smem);
    const int tid = threadIdx.x, lane = tid & 31, wid = tid >> 5;
    const int m0 = blockIdx.y * 128, n0 = blockIdx.x * 128;
    const int wm = (wid & 1) * 64;
    const int wn = (wid >> 1) * 32;

    float acc[4][4][4];
#pragma unroll
    for (int i = 0; i < 4; i++)
#pragma unroll
        for (int j = 0; j < 4; j++)
#pragma unroll
            for (int k = 0; k < 4; k++) acc[i][j][k] = 0.f;

    const __nv_bfloat16* srcHi;
    const __nv_bfloat16* srcLo;
    if (tid < 128) {
        srcHi = g_xhi + (size_t)(m0 + tid) * NI;
        srcLo = g_xlo + (size_t)(m0 + tid) * NI;
    } else {
        srcHi = g_whi + (size_t)(n0 + tid - 128) * NI;
        srcLo = g_wlo + (size_t)(n0 + tid - 128) * NI;
    }

    auto load_chunk = [&](int c) {
        uint32_t base = sb + (uint32_t)(c & (NSTAGE - 1)) * STAGE_B;
        const __nv_bfloat16* ph = srcHi + c * BK;
        const __nv_bfloat16* pl = srcLo + c * BK;
#pragma unroll
        for (int j = 0; j < 4; j++) {
            cp_async16(base + SWZ((uint32_t)(tid * 128 + j * 16)), ph + j * 8);
            cp_async16(base + SWZ((uint32_t)(tid * 128 + 64 + j * 16)), pl + j * 8);
        }
        asm volatile("cp.async.commit_group;" ::: "memory");
    };

    const int a_row = wm + (lane & 15);
    const int a_cb  = (lane >> 4) * 16;
    const int b_row = 128 + wn + (lane & 7) + ((lane >> 4) * 8);
    const int b_cb  = ((lane >> 3) & 1) * 16;

    // prologue: fill NSTAGE-1 stages
    load_chunk(0);
    load_chunk(1);
    load_chunk(2);

    for (int c = 0; c < NCHUNK; c++) {
        asm volatile("cp.async.wait_group %0;" :: "n"(NSTAGE - 2) : "memory"); // chunk c ready
        __syncthreads();  // also: all warps done computing chunk c-1 -> its stage reusable

        if (c + NSTAGE - 1 < NCHUNK) {
            load_chunk(c + NSTAGE - 1);
        } else {
            asm volatile("cp.async.commit_group;" ::: "memory"); // keep group count in lockstep
        }

        uint32_t base = sb + (uint32_t)(c & (NSTAGE - 1)) * STAGE_B;
#pragma unroll
        for (int kk = 0; kk < BK; kk += 16) {
            uint32_t ah[4][4], al[4][4], bh[4][2], bl[4][2];
#pragma unroll
            for (int mt = 0; mt < 4; mt++) {
                uint32_t off = (uint32_t)((a_row + mt * 16) * 128 + a_cb + kk * 2);
                ldsm_x4(ah[mt], base + SWZ(off));
                ldsm_x4(al[mt], base + SWZ(off + 64));
            }
#pragma unroll
            for (int p = 0; p < 2; p++) {
                uint32_t off = (uint32_t)((b_row + p * 16) * 128 + b_cb + kk * 2);
                uint32_t t4[4];
                ldsm_x4(t4, base + SWZ(off));
                bh[2 * p][0] = t4[0]; bh[2 * p][1] = t4[1];
                bh[2 * p + 1][0] = t4[2]; bh[2 * p + 1][1] = t4[3];
                ldsm_x4(t4, base + SWZ(off + 64));
                bl[2 * p][0] = t4[0]; bl[2 * p][1] = t4[1];
                bl[2 * p + 1][0] = t4[2]; bl[2 * p + 1][1] = t4[3];
            }
#pragma unroll
            for (int mt = 0; mt < 4; mt++)
#pragma unroll
                for (int nt = 0; nt < 4; nt++) {
                    mma16816(acc[mt][nt], ah[mt], bh[nt]);
                    mma16816(acc[mt][nt], ah[mt], bl[nt]);
                    mma16816(acc[mt][nt], al[mt], bh[nt]);
                }
        }
    }

    // Epilogue
    const int erow = m0 + wm + (lane >> 2);
    const int ecol0 = n0 + wn + (lane & 3) * 2;
    float2 brg[4];
#pragma unroll
    for (int nt = 0; nt < 4; nt++)
        brg[nt] = *(const float2*)(bias + ecol0 + nt * 8);
#pragma unroll
    for (int mt = 0; mt < 4; mt++) {
        int r0 = erow + mt * 16;
#pragma unroll
        for (int nt = 0; nt < 4; nt++) {
            float2 v0 = {acc[mt][nt][0] + brg[nt].x, acc[mt][nt][1] + brg[nt].y};
            float2 v1 = {acc[mt][nt][2] + brg[nt].x, acc[mt][nt][3] + brg[nt].y};
            *(float2*)(g_cur + (size_t)r0 * NN + ecol0 + nt * 8) = v0;
            *(float2*)(g_cur + (size_t)(r0 + 8) * NN + ecol0 + nt * 8) = v1;
        }
    }
}

// ---------------------------------------------------------------------------
// ALIF scan: 64 CTAs x 128 threads, 4 neurons/thread.
// Time loop manually unrolled x8 so the prefetch ring cpre[] is statically
// indexed (stays in registers — dynamic indexing demotes to local memory).
// ---------------------------------------------------------------------------
__global__ __launch_bounds__(128) void alif_scan(const float* __restrict__ beta,
                                                 const float* __restrict__ beta2,
                                                 const float* __restrict__ decay_v,
                                                 const float* __restrict__ decay_b,
                                                 float* __restrict__ out) {
    const int b = blockIdx.x;
    const int tid = threadIdx.x;
    const int w = tid >> 5, lane = tid & 31;

    __shared__ int wsum[4];
    __shared__ int act[NN];

    const float4 be = ((const float4*)beta)[tid];
    const float4 b2 = ((const float4*)beta2)[tid];
    const float4 dv = ((const float4*)decay_v)[tid];
    const float4 db = ((const float4*)decay_b)[tid];
    const float4 omdv = {1.f - dv.x, 1.f - dv.y, 1.f - dv.z, 1.f - dv.w};
    const float4 omdb = {1.f - db.x, 1.f - db.y, 1.f - db.z, 1.f - db.w};

    float4 v  = {0.f, 0.f, 0.f, 0.f};
    float4 bb = {0.f, 0.f, 0.f, 0.f};
    float4 zp = {0.f, 0.f, 0.f, 0.f};
    int nact = 0;

    const float4* cur4 = (const float4*)(g_cur + (size_t)b * NT * NN);
    const float4* Rt4  = (const float4*)g_Rt;

    float* zsb = out + (size_t)b * NT * NN;
    float* vf  = out + ZS_ELEMS + (size_t)(0 * NB + b) * ST_STRIDE;
    float* zf  = out + ZS_ELEMS + (size_t)(1 * NB + b) * ST_STRIDE;
    float* bf  = out + ZS_ELEMS + (size_t)(2 * NB + b) * ST_STRIDE;

    const float4 zero4 = {0.f, 0.f, 0.f, 0.f};
    ((float4*)vf)[tid] = zero4;
    ((float4*)zf)[tid] = zero4;
    ((float4*)bf)[tid] = zero4;

    float4 cpre[8];
#pragma unroll
    for (int i = 0; i < 8; i++) cpre[i] = cur4[(size_t)i * 128 + tid];

    for (int tb = 0; tb < NT; tb += 8) {
#pragma unroll
        for (int u = 0; u < 8; u++) {
            const int t = tb + u;
            float4 c = cpre[u];
            if (t + 8 < NT) cpre[u] = cur4[(size_t)(t + 8) * 128 + tid];

            float4 rec = {0.f, 0.f, 0.f, 0.f};
            for (int k = 0; k < nact; k++) {
                float4 r = Rt4[(size_t)act[k] * 128 + tid];
                rec.x += r.x; rec.y += r.y; rec.z += r.z; rec.w += r.w;
            }

            v.x *= (1.f - zp.x); v.y *= (1.f - zp.y); v.z *= (1.f - zp.z); v.w *= (1.f - zp.w);
            float4 vt;
            vt.x = dv.x * v.x + omdv.x * ((c.x + rec.x) - bb.x);
            vt.y = dv.y * v.y + omdv.y * ((c.y + rec.y) - bb.y);
            vt.z = dv.z * v.z + omdv.z * ((c.z + rec.z) - bb.z);
            vt.w = dv.w * v.w + omdv.w * ((c.w + rec.w) - bb.w);
            float4 zt;
            zt.x = (vt.x >= 1.0f) ? 1.f : 0.f;
            zt.y = (vt.y >= 1.0f) ? 1.f : 0.f;
            zt.z = (vt.z >= 1.0f) ? 1.f : 0.f;
            zt.w = (vt.w >= 1.0f) ? 1.f : 0.f;
            bb.x = db.x * bb.x + omdb.x * (be.x * vt.x + b2.x * zt.x);
            bb.y = db.y * bb.y + omdb.y * (be.y * vt.y + b2.y * zt.y);
            bb.z = db.z * bb.z + omdb.z * (be.z * vt.z + b2.z * zt.z);
            bb.w = db.w * bb.w + omdb.w * (be.w * vt.w + b2.w * zt.w);
            v = vt; zp = zt;

            ((float4*)zsb)[(size_t)t * 128 + tid] = zt;
            size_t tpo = (size_t)(t + 1) * 128 + tid;
            ((float4*)vf)[tpo] = vt;
            ((float4*)zf)[tpo] = zt;
            ((float4*)bf)[tpo] = bb;

            int any = (zt.x != 0.f) | (zt.y != 0.f) | (zt.z != 0.f) | (zt.w != 0.f);
            int flag = __syncthreads_count(any);
            if (flag) {
                int myspk = (zt.x != 0.f) + (zt.y != 0.f) + (zt.z != 0.f) + (zt.w != 0.f);
                int incl = myspk;
#pragma unroll
                for (int d = 1; d < 32; d <<= 1) {
                    int n = __shfl_up_sync(0xffffffffu, incl, d);
                    if (lane >= d) incl += n;
                }
                if (lane == 31) wsum[w] = incl;
                __syncthreads();
                int basep = 0, tot = 0;
#pragma unroll
                for (int i = 0; i < 4; i++) {
                    int sv = wsum[i];
                    if (i < w) basep += sv;
                    tot += sv;
                }
                int pos = basep + incl - myspk;
                int o0 = tid * 4;
                if (zt.x != 0.f) act[pos++] = o0 + 0;
                if (zt.y != 0.f) act[pos++] = o0 + 1;
                if (zt.z != 0.f) act[pos++] = o0 + 2;
                if (zt.w != 0.f) act[pos++] = o0 + 3;
                __syncthreads();
                nact = tot;
            } else {
                nact = 0;
            }
        }
    }
}

// ---------------------------------------------------------------------------
extern "C" void kernel_launch(void* const* d_in, const int* in_sizes, int n_in,
                              void* d_out, int out_size) {
    const float* x     = (const float*)d_in[0];
    const float* W     = (const float*)d_in[1];
    const float* bias  = (const float*)d_in[2];
    const float* R     = (const float*)d_in[3];
    const float* beta  = (const float*)d_in[4];
    const float* beta2 = (const float*)d_in[5];
    const float* dvp   = (const float*)d_in[6];
    const float* dbp   = (const float*)d_in[7];
    float* out = (float*)d_out;

    cudaFuncSetAttribute(gemm_tc, cudaFuncAttributeMaxDynamicSharedMemorySize, GEMM_SMEM);

    dim3 tgrid(NN / 32, NN / 32), tblk(32, 32);
    transpose_R<<<tgrid, tblk>>>(R);

    convert_x<<<(NM * NI / 4) / 256, 256>>>(x);
    convert_w<<<(NN * NI / 4) / 256, 256>>>(W);

    dim3 ggrid(NN / 128, NM / 128);
    gemm_tc<<<ggrid, 256, GEMM_SMEM>>>(bias);

    alif_scan<<<NB, 128>>>(beta, beta2, dvp, dbp, out);
}

// round 5
// speedup vs baseline: 2.4468x; 1.4620x over previous
#include <cuda_runtime.h>
#include <cuda_bf16.h>
#include <cstdint>

// Problem constants
#define NB   64
#define NT   1000
#define NN   512
#define NI   512
#define NM   (NB*NT)

#define ZS_ELEMS   (NB*NT*NN)
#define ST_STRIDE  ((NT+1)*NN)

// ---------------------------------------------------------------------------
// Scratch (device globals — no allocation allowed)
// ---------------------------------------------------------------------------
__device__ float         g_cur[(size_t)NM * NN];
__device__ float         g_Rt[NN * NN];
__device__ __nv_bfloat16 g_xhi[(size_t)NM * NI];
__device__ __nv_bfloat16 g_xlo[(size_t)NM * NI];
__device__ __nv_bfloat16 g_whi[NN * NI];
__device__ __nv_bfloat16 g_wlo[NN * NI];

// ---------------------------------------------------------------------------
// Portable PTX helpers (sm_80+ only — tcgen05 unavailable at compute_103)
// ---------------------------------------------------------------------------
__device__ __forceinline__ uint32_t smem_to_u32(const void* p) {
    uint32_t a;
    asm("{ .reg .u64 t; cvta.to.shared.u64 t, %1; cvt.u32.u64 %0, t; }" : "=r"(a) : "l"(p));
    return a;
}
__device__ __forceinline__ void cp_async16(uint32_t dst, const void* src) {
    asm volatile("cp.async.cg.shared.global [%0], [%1], 16;" :: "r"(dst), "l"(src) : "memory");
}
__device__ __forceinline__ void ldsm_x4(uint32_t r[4], uint32_t addr) {
    asm volatile("ldmatrix.sync.aligned.m8n8.x4.shared.b16 {%0,%1,%2,%3}, [%4];"
        : "=r"(r[0]), "=r"(r[1]), "=r"(r[2]), "=r"(r[3]) : "r"(addr));
}
__device__ __forceinline__ void mma16816(float d[4], const uint32_t a[4], const uint32_t b[2]) {
    asm volatile("mma.sync.aligned.m16n8k16.row.col.f32.bf16.bf16.f32 "
        "{%0,%1,%2,%3}, {%4,%5,%6,%7}, {%8,%9}, {%0,%1,%2,%3};"
        : "+f"(d[0]), "+f"(d[1]), "+f"(d[2]), "+f"(d[3])
        : "r"(a[0]), "r"(a[1]), "r"(a[2]), "r"(a[3]), "r"(b[0]), "r"(b[1]));
}
#define SWZ(off) ((off) ^ (((off) >> 3) & 0x70))

// ---------------------------------------------------------------------------
// R transpose
// ---------------------------------------------------------------------------
__global__ void transpose_R(const float* __restrict__ R) {
    __shared__ float tile[32][33];
    int bx = blockIdx.x * 32, by = blockIdx.y * 32;
    tile[threadIdx.y][threadIdx.x] = R[(by + threadIdx.y) * NN + bx + threadIdx.x];
    __syncthreads();
    g_Rt[(bx + threadIdx.y) * NN + (by + threadIdx.x)] = tile[threadIdx.x][threadIdx.y];
}

// ---------------------------------------------------------------------------
// fp32 -> bf16 hi + bf16 lo splits
// ---------------------------------------------------------------------------
__device__ __forceinline__ void split4(float4 v, ushort4& hv, ushort4& lv) {
    __nv_bfloat16 h0 = __float2bfloat16(v.x), h1 = __float2bfloat16(v.y);
    __nv_bfloat16 h2 = __float2bfloat16(v.z), h3 = __float2bfloat16(v.w);
    hv.x = __bfloat16_as_ushort(h0); hv.y = __bfloat16_as_ushort(h1);
    hv.z = __bfloat16_as_ushort(h2); hv.w = __bfloat16_as_ushort(h3);
    lv.x = __bfloat16_as_ushort(__float2bfloat16(v.x - __bfloat162float(h0)));
    lv.y = __bfloat16_as_ushort(__float2bfloat16(v.y - __bfloat162float(h1)));
    lv.z = __bfloat16_as_ushort(__float2bfloat16(v.z - __bfloat162float(h2)));
    lv.w = __bfloat16_as_ushort(__float2bfloat16(v.w - __bfloat162float(h3)));
}
__global__ __launch_bounds__(256) void convert_x(const float* __restrict__ src) {
    int i = blockIdx.x * 256 + threadIdx.x;
    ushort4 hv, lv;
    split4(((const float4*)src)[i], hv, lv);
    ((ushort4*)g_xhi)[i] = hv;
    ((ushort4*)g_xlo)[i] = lv;
}
__global__ __launch_bounds__(256) void convert_w(const float* __restrict__ src) {
    int i = blockIdx.x * 256 + threadIdx.x;
    ushort4 hv, lv;
    split4(((const float4*)src)[i], hv, lv);
    ((ushort4*)g_whi)[i] = hv;
    ((ushort4*)g_wlo)[i] = lv;
}

// ---------------------------------------------------------------------------
// bf16-split GEMM via mma.sync, 4-stage cp.async pipeline.
// Pass-major MMA ordering: consecutive HMMAs hit different accumulators
// (in-order issue never stalls on an accumulator RAW).
// ---------------------------------------------------------------------------
#define BK       32
#define NCHUNK   (NI / BK)       // 16
#define NSTAGE   4
#define STAGE_B  32768
#define GEMM_SMEM (NSTAGE * STAGE_B)   // 131072

__global__ __launch_bounds__(256) void gemm_tc(const float* __restrict__ bias) {
    extern __shared__ char smem[];
    uint32_t sb = smem_to_u32(smem);
    const int tid = threadIdx.x, lane = tid & 31, wid = tid >> 5;
    const int m0 = blockIdx.y * 128, n0 = blockIdx.x * 128;
    const int wm = (wid & 1) * 64;
    const int wn = (wid >> 1) * 32;

    float acc[4][4][4];
#pragma unroll
    for (int i = 0; i < 4; i++)
#pragma unroll
        for (int j = 0; j < 4; j++)
#pragma unroll
            for (int k = 0; k < 4; k++) acc[i][j][k] = 0.f;

    const __nv_bfloat16* srcHi;
    const __nv_bfloat16* srcLo;
    if (tid < 128) {
        srcHi = g_xhi + (size_t)(m0 + tid) * NI;
        srcLo = g_xlo + (size_t)(m0 + tid) * NI;
    } else {
        srcHi = g_whi + (size_t)(n0 + tid - 128) * NI;
        srcLo = g_wlo + (size_t)(n0 + tid - 128) * NI;
    }

    auto load_chunk = [&](int c) {
        uint32_t base = sb + (uint32_t)(c & (NSTAGE - 1)) * STAGE_B;
        const __nv_bfloat16* ph = srcHi + c * BK;
        const __nv_bfloat16* pl = srcLo + c * BK;
#pragma unroll
        for (int j = 0; j < 4; j++) {
            cp_async16(base + SWZ((uint32_t)(tid * 128 + j * 16)), ph + j * 8);
            cp_async16(base + SWZ((uint32_t)(tid * 128 + 64 + j * 16)), pl + j * 8);
        }
        asm volatile("cp.async.commit_group;" ::: "memory");
    };

    const int a_row = wm + (lane & 15);
    const int a_cb  = (lane >> 4) * 16;
    const int b_row = 128 + wn + (lane & 7) + ((lane >> 4) * 8);
    const int b_cb  = ((lane >> 3) & 1) * 16;

    load_chunk(0);
    load_chunk(1);
    load_chunk(2);

    for (int c = 0; c < NCHUNK; c++) {
        asm volatile("cp.async.wait_group %0;" :: "n"(NSTAGE - 2) : "memory");
        __syncthreads();

        if (c + NSTAGE - 1 < NCHUNK) {
            load_chunk(c + NSTAGE - 1);
        } else {
            asm volatile("cp.async.commit_group;" ::: "memory");
        }

        uint32_t base = sb + (uint32_t)(c & (NSTAGE - 1)) * STAGE_B;
#pragma unroll
        for (int kk = 0; kk < BK; kk += 16) {
            uint32_t ah[4][4], al[4][4], bh[4][2], bl[4][2];
#pragma unroll
            for (int mt = 0; mt < 4; mt++) {
                uint32_t off = (uint32_t)((a_row + mt * 16) * 128 + a_cb + kk * 2);
                ldsm_x4(ah[mt], base + SWZ(off));
                ldsm_x4(al[mt], base + SWZ(off + 64));
            }
#pragma unroll
            for (int p = 0; p < 2; p++) {
                uint32_t off = (uint32_t)((b_row + p * 16) * 128 + b_cb + kk * 2);
                uint32_t t4[4];
                ldsm_x4(t4, base + SWZ(off));
                bh[2 * p][0] = t4[0]; bh[2 * p][1] = t4[1];
                bh[2 * p + 1][0] = t4[2]; bh[2 * p + 1][1] = t4[3];
                ldsm_x4(t4, base + SWZ(off + 64));
                bl[2 * p][0] = t4[0]; bl[2 * p][1] = t4[1];
                bl[2 * p + 1][0] = t4[2]; bl[2 * p + 1][1] = t4[3];
            }
            // pass-major: 16 independent MMAs between reuses of any acc tile
#pragma unroll
            for (int mt = 0; mt < 4; mt++)
#pragma unroll
                for (int nt = 0; nt < 4; nt++)
                    mma16816(acc[mt][nt], ah[mt], bh[nt]);
#pragma unroll
            for (int mt = 0; mt < 4; mt++)
#pragma unroll
                for (int nt = 0; nt < 4; nt++)
                    mma16816(acc[mt][nt], ah[mt], bl[nt]);
#pragma unroll
            for (int mt = 0; mt < 4; mt++)
#pragma unroll
                for (int nt = 0; nt < 4; nt++)
                    mma16816(acc[mt][nt], al[mt], bh[nt]);
        }
    }

    // Epilogue
    const int erow = m0 + wm + (lane >> 2);
    const int ecol0 = n0 + wn + (lane & 3) * 2;
    float2 brg[4];
#pragma unroll
    for (int nt = 0; nt < 4; nt++)
        brg[nt] = *(const float2*)(bias + ecol0 + nt * 8);
#pragma unroll
    for (int mt = 0; mt < 4; mt++) {
        int r0 = erow + mt * 16;
#pragma unroll
        for (int nt = 0; nt < 4; nt++) {
            float2 v0 = {acc[mt][nt][0] + brg[nt].x, acc[mt][nt][1] + brg[nt].y};
            float2 v1 = {acc[mt][nt][2] + brg[nt].x, acc[mt][nt][3] + brg[nt].y};
            *(float2*)(g_cur + (size_t)r0 * NN + ecol0 + nt * 8) = v0;
            *(float2*)(g_cur + (size_t)(r0 + 8) * NN + ecol0 + nt * 8) = v1;
        }
    }
}

// ---------------------------------------------------------------------------
// ALIF scan: 64 CTAs x 128 threads, 4 neurons/thread, x8 unrolled time loop
// (statically-indexed register prefetch ring).
// ---------------------------------------------------------------------------
__global__ __launch_bounds__(128) void alif_scan(const float* __restrict__ beta,
                                                 const float* __restrict__ beta2,
                                                 const float* __restrict__ decay_v,
                                                 const float* __restrict__ decay_b,
                                                 float* __restrict__ out) {
    const int b = blockIdx.x;
    const int tid = threadIdx.x;
    const int w = tid >> 5, lane = tid & 31;

    __shared__ int wsum[4];
    __shared__ int act[NN];

    const float4 be = ((const float4*)beta)[tid];
    const float4 b2 = ((const float4*)beta2)[tid];
    const float4 dv = ((const float4*)decay_v)[tid];
    const float4 db = ((const float4*)decay_b)[tid];
    const float4 omdv = {1.f - dv.x, 1.f - dv.y, 1.f - dv.z, 1.f - dv.w};
    const float4 omdb = {1.f - db.x, 1.f - db.y, 1.f - db.z, 1.f - db.w};

    float4 v  = {0.f, 0.f, 0.f, 0.f};
    float4 bb = {0.f, 0.f, 0.f, 0.f};
    float4 zp = {0.f, 0.f, 0.f, 0.f};
    int nact = 0;

    const float4* cur4 = (const float4*)(g_cur + (size_t)b * NT * NN);
    const float4* Rt4  = (const float4*)g_Rt;

    float* zsb = out + (size_t)b * NT * NN;
    float* vf  = out + ZS_ELEMS + (size_t)(0 * NB + b) * ST_STRIDE;
    float* zf  = out + ZS_ELEMS + (size_t)(1 * NB + b) * ST_STRIDE;
    float* bf  = out + ZS_ELEMS + (size_t)(2 * NB + b) * ST_STRIDE;

    const float4 zero4 = {0.f, 0.f, 0.f, 0.f};
    ((float4*)vf)[tid] = zero4;
    ((float4*)zf)[tid] = zero4;
    ((float4*)bf)[tid] = zero4;

    float4 cpre[8];
#pragma unroll
    for (int i = 0; i < 8; i++) cpre[i] = cur4[(size_t)i * 128 + tid];

    for (int tb = 0; tb < NT; tb += 8) {
#pragma unroll
        for (int u = 0; u < 8; u++) {
            const int t = tb + u;
            float4 c = cpre[u];
            if (t + 8 < NT) cpre[u] = cur4[(size_t)(t + 8) * 128 + tid];

            float4 rec = {0.f, 0.f, 0.f, 0.f};
            for (int k = 0; k < nact; k++) {
                float4 r = Rt4[(size_t)act[k] * 128 + tid];
                rec.x += r.x; rec.y += r.y; rec.z += r.z; rec.w += r.w;
            }

            v.x *= (1.f - zp.x); v.y *= (1.f - zp.y); v.z *= (1.f - zp.z); v.w *= (1.f - zp.w);
            float4 vt;
            vt.x = dv.x * v.x + omdv.x * ((c.x + rec.x) - bb.x);
            vt.y = dv.y * v.y + omdv.y * ((c.y + rec.y) - bb.y);
            vt.z = dv.z * v.z + omdv.z * ((c.z + rec.z) - bb.z);
            vt.w = dv.w * v.w + omdv.w * ((c.w + rec.w) - bb.w);
            float4 zt;
            zt.x = (vt.x >= 1.0f) ? 1.f : 0.f;
            zt.y = (vt.y >= 1.0f) ? 1.f : 0.f;
            zt.z = (vt.z >= 1.0f) ? 1.f : 0.f;
            zt.w = (vt.w >= 1.0f) ? 1.f : 0.f;
            bb.x = db.x * bb.x + omdb.x * (be.x * vt.x + b2.x * zt.x);
            bb.y = db.y * bb.y + omdb.y * (be.y * vt.y + b2.y * zt.y);
            bb.z = db.z * bb.z + omdb.z * (be.z * vt.z + b2.z * zt.z);
            bb.w = db.w * bb.w + omdb.w * (be.w * vt.w + b2.w * zt.w);
            v = vt; zp = zt;

            ((float4*)zsb)[(size_t)t * 128 + tid] = zt;
            size_t tpo = (size_t)(t + 1) * 128 + tid;
            ((float4*)vf)[tpo] = vt;
            ((float4*)zf)[tpo] = zt;
            ((float4*)bf)[tpo] = bb;

            int any = (zt.x != 0.f) | (zt.y != 0.f) | (zt.z != 0.f) | (zt.w != 0.f);
            int flag = __syncthreads_count(any);
            if (flag) {
                int myspk = (zt.x != 0.f) + (zt.y != 0.f) + (zt.z != 0.f) + (zt.w != 0.f);
                int incl = myspk;
#pragma unroll
                for (int d = 1; d < 32; d <<= 1) {
                    int n = __shfl_up_sync(0xffffffffu, incl, d);
                    if (lane >= d) incl += n;
                }
                if (lane == 31) wsum[w] = incl;
                __syncthreads();
                int basep = 0, tot = 0;
#pragma unroll
                for (int i = 0; i < 4; i++) {
                    int sv = wsum[i];
                    if (i < w) basep += sv;
                    tot += sv;
                }
                int pos = basep + incl - myspk;
                int o0 = tid * 4;
                if (zt.x != 0.f) act[pos++] = o0 + 0;
                if (zt.y != 0.f) act[pos++] = o0 + 1;
                if (zt.z != 0.f) act[pos++] = o0 + 2;
                if (zt.w != 0.f) act[pos++] = o0 + 3;
                __syncthreads();
                nact = tot;
            } else {
                nact = 0;
            }
        }
    }
}

// ---------------------------------------------------------------------------
extern "C" void kernel_launch(void* const* d_in, const int* in_sizes, int n_in,
                              void* d_out, int out_size) {
    const float* x     = (const float*)d_in[0];
    const float* W     = (const float*)d_in[1];
    const float* bias  = (const float*)d_in[2];
    const float* R     = (const float*)d_in[3];
    const float* beta  = (const float*)d_in[4];
    const float* beta2 = (const float*)d_in[5];
    const float* dvp   = (const float*)d_in[6];
    const float* dbp   = (const float*)d_in[7];
    float* out = (float*)d_out;

    cudaFuncSetAttribute(gemm_tc, cudaFuncAttributeMaxDynamicSharedMemorySize, GEMM_SMEM);

    dim3 tgrid(NN / 32, NN / 32), tblk(32, 32);
    transpose_R<<<tgrid, tblk>>>(R);

    convert_x<<<(NM * NI / 4) / 256, 256>>>(x);
    convert_w<<<(NN * NI / 4) / 256, 256>>>(W);

    dim3 ggrid(NN / 128, NM / 128);
    gemm_tc<<<ggrid, 256, GEMM_SMEM>>>(bias);

    alif_scan<<<NB, 128>>>(beta, beta2, dvp, dbp, out);
}

// round 6
// speedup vs baseline: 2.4762x; 1.0120x over previous
#include <cuda_runtime.h>
#include <cuda_bf16.h>
#include <cstdint>

// Problem constants
#define NB   64
#define NT   1000
#define NN   512
#define NI   512
#define NM   (NB*NT)

#define ZS_ELEMS   (NB*NT*NN)
#define ST_STRIDE  ((NT+1)*NN)

// ---------------------------------------------------------------------------
// Scratch (device globals — no allocation allowed)
// ---------------------------------------------------------------------------
__device__ float         g_cur[(size_t)NM * NN];
__device__ float         g_Rt[NN * NN];
__device__ __nv_bfloat16 g_xhi[(size_t)NM * NI];
__device__ __nv_bfloat16 g_xlo[(size_t)NM * NI];
__device__ __nv_bfloat16 g_whi[NN * NI];
__device__ __nv_bfloat16 g_wlo[NN * NI];

// ---------------------------------------------------------------------------
// Portable PTX helpers (sm_80+ only — tcgen05 unavailable at compute_103)
// ---------------------------------------------------------------------------
__device__ __forceinline__ uint32_t smem_to_u32(const void* p) {
    uint32_t a;
    asm("{ .reg .u64 t; cvta.to.shared.u64 t, %1; cvt.u32.u64 %0, t; }" : "=r"(a) : "l"(p));
    return a;
}
__device__ __forceinline__ void cp_async16(uint32_t dst, const void* src) {
    asm volatile("cp.async.cg.shared.global [%0], [%1], 16;" :: "r"(dst), "l"(src) : "memory");
}
__device__ __forceinline__ void ldsm_x4(uint32_t r[4], uint32_t addr) {
    asm volatile("ldmatrix.sync.aligned.m8n8.x4.shared.b16 {%0,%1,%2,%3}, [%4];"
        : "=r"(r[0]), "=r"(r[1]), "=r"(r[2]), "=r"(r[3]) : "r"(addr));
}
__device__ __forceinline__ void mma16816(float d[4], const uint32_t a[4], const uint32_t b[2]) {
    asm volatile("mma.sync.aligned.m16n8k16.row.col.f32.bf16.bf16.f32 "
        "{%0,%1,%2,%3}, {%4,%5,%6,%7}, {%8,%9}, {%0,%1,%2,%3};"
        : "+f"(d[0]), "+f"(d[1]), "+f"(d[2]), "+f"(d[3])
        : "r"(a[0]), "r"(a[1]), "r"(a[2]), "r"(a[3]), "r"(b[0]), "r"(b[1]));
}
#define SWZ(off) ((off) ^ (((off) >> 3) & 0x70))

// ---------------------------------------------------------------------------
// R transpose
// ---------------------------------------------------------------------------
__global__ void transpose_R(const float* __restrict__ R) {
    __shared__ float tile[32][33];
    int bx = blockIdx.x * 32, by = blockIdx.y * 32;
    tile[threadIdx.y][threadIdx.x] = R[(by + threadIdx.y) * NN + bx + threadIdx.x];
    __syncthreads();
    g_Rt[(bx + threadIdx.y) * NN + (by + threadIdx.x)] = tile[threadIdx.x][threadIdx.y];
}

// ---------------------------------------------------------------------------
// fp32 -> bf16 hi + bf16 lo splits
// ---------------------------------------------------------------------------
__device__ __forceinline__ void split4(float4 v, ushort4& hv, ushort4& lv) {
    __nv_bfloat16 h0 = __float2bfloat16(v.x), h1 = __float2bfloat16(v.y);
    __nv_bfloat16 h2 = __float2bfloat16(v.z), h3 = __float2bfloat16(v.w);
    hv.x = __bfloat16_as_ushort(h0); hv.y = __bfloat16_as_ushort(h1);
    hv.z = __bfloat16_as_ushort(h2); hv.w = __bfloat16_as_ushort(h3);
    lv.x = __bfloat16_as_ushort(__float2bfloat16(v.x - __bfloat162float(h0)));
    lv.y = __bfloat16_as_ushort(__float2bfloat16(v.y - __bfloat162float(h1)));
    lv.z = __bfloat16_as_ushort(__float2bfloat16(v.z - __bfloat162float(h2)));
    lv.w = __bfloat16_as_ushort(__float2bfloat16(v.w - __bfloat162float(h3)));
}
__global__ __launch_bounds__(256) void convert_x(const float* __restrict__ src) {
    int i = blockIdx.x * 256 + threadIdx.x;
    ushort4 hv, lv;
    split4(((const float4*)src)[i], hv, lv);
    ((ushort4*)g_xhi)[i] = hv;
    ((ushort4*)g_xlo)[i] = lv;
}
__global__ __launch_bounds__(256) void convert_w(const float* __restrict__ src) {
    int i = blockIdx.x * 256 + threadIdx.x;
    ushort4 hv, lv;
    split4(((const float4*)src)[i], hv, lv);
    ((ushort4*)g_whi)[i] = hv;
    ((ushort4*)g_wlo)[i] = lv;
}

// ---------------------------------------------------------------------------
// bf16-split GEMM via mma.sync.
// 128-thread CTA, tile 128x64, 4 warps (2m x 2n), warp tile 64x32.
// 3-stage cp.async pipeline, 24KB/stage -> 72KB smem -> 3 CTAs/SM so
// independent CTAs cover each other's LDSM/barrier bubbles.
// Stage layout: 192 rows x 128B; rows 0-127 = A (hi 64B | lo 64B), 128-191 = B.
// ---------------------------------------------------------------------------
#define BK       32
#define NCHUNK   (NI / BK)       // 16
#define NSTAGE   3
#define STAGE_B  (192 * 128)     // 24576
#define GEMM_SMEM (NSTAGE * STAGE_B)   // 73728

__global__ __launch_bounds__(128, 3) void gemm_tc(const float* __restrict__ bias) {
    extern __shared__ char smem[];
    uint32_t sb = smem_to_u32(smem);
    const int tid = threadIdx.x, lane = tid & 31, wid = tid >> 5;
    const int m0 = blockIdx.y * 128, n0 = blockIdx.x * 64;
    const int wm = (wid & 1) * 64;
    const int wn = (wid >> 1) * 32;

    float acc[4][4][4];
#pragma unroll
    for (int i = 0; i < 4; i++)
#pragma unroll
        for (int j = 0; j < 4; j++)
#pragma unroll
            for (int k = 0; k < 4; k++) acc[i][j][k] = 0.f;

    // loader: thread t owns A row t; threads 0-63 additionally own B row 128+t
    const __nv_bfloat16* ph0 = g_xhi + (size_t)(m0 + tid) * NI;
    const __nv_bfloat16* pl0 = g_xlo + (size_t)(m0 + tid) * NI;
    const bool hasB = (tid < 64);
    const __nv_bfloat16* ph1 = g_whi + (size_t)(n0 + (tid & 63)) * NI;
    const __nv_bfloat16* pl1 = g_wlo + (size_t)(n0 + (tid & 63)) * NI;
    const uint32_t rowOff0 = (uint32_t)tid * 128;
    const uint32_t rowOff1 = (uint32_t)(128 + tid) * 128;

    auto load_chunk = [&](int c) {
        uint32_t base = sb + (uint32_t)(c % NSTAGE) * STAGE_B;
#pragma unroll
        for (int j = 0; j < 4; j++) {
            cp_async16(base + SWZ(rowOff0 + j * 16), ph0 + c * BK + j * 8);
            cp_async16(base + SWZ(rowOff0 + 64 + j * 16), pl0 + c * BK + j * 8);
        }
        if (hasB) {
#pragma unroll
            for (int j = 0; j < 4; j++) {
                cp_async16(base + SWZ(rowOff1 + j * 16), ph1 + c * BK + j * 8);
                cp_async16(base + SWZ(rowOff1 + 64 + j * 16), pl1 + c * BK + j * 8);
            }
        }
        asm volatile("cp.async.commit_group;" ::: "memory");
    };

    const int a_row = wm + (lane & 15);
    const int a_cb  = (lane >> 4) * 16;
    const int b_row = 128 + wn + (lane & 7) + ((lane >> 4) * 8);
    const int b_cb  = ((lane >> 3) & 1) * 16;

    load_chunk(0);
    load_chunk(1);

    for (int c = 0; c < NCHUNK; c++) {
        asm volatile("cp.async.wait_group %0;" :: "n"(NSTAGE - 2) : "memory");
        __syncthreads();

        if (c + NSTAGE - 1 < NCHUNK) {
            load_chunk(c + NSTAGE - 1);
        } else {
            asm volatile("cp.async.commit_group;" ::: "memory");
        }

        uint32_t base = sb + (uint32_t)(c % NSTAGE) * STAGE_B;
#pragma unroll
        for (int kk = 0; kk < BK; kk += 16) {
            uint32_t ah[4][4], al[4][4], bh[4][2], bl[4][2];
#pragma unroll
            for (int mt = 0; mt < 4; mt++) {
                uint32_t off = (uint32_t)((a_row + mt * 16) * 128 + a_cb + kk * 2);
                ldsm_x4(ah[mt], base + SWZ(off));
                ldsm_x4(al[mt], base + SWZ(off + 64));
            }
#pragma unroll
            for (int p = 0; p < 2; p++) {
                uint32_t off = (uint32_t)((b_row + p * 16) * 128 + b_cb + kk * 2);
                uint32_t t4[4];
                ldsm_x4(t4, base + SWZ(off));
                bh[2 * p][0] = t4[0]; bh[2 * p][1] = t4[1];
                bh[2 * p + 1][0] = t4[2]; bh[2 * p + 1][1] = t4[3];
                ldsm_x4(t4, base + SWZ(off + 64));
                bl[2 * p][0] = t4[0]; bl[2 * p][1] = t4[1];
                bl[2 * p + 1][0] = t4[2]; bl[2 * p + 1][1] = t4[3];
            }
            // pass-major: consecutive MMAs hit different accumulators
#pragma unroll
            for (int mt = 0; mt < 4; mt++)
#pragma unroll
                for (int nt = 0; nt < 4; nt++)
                    mma16816(acc[mt][nt], ah[mt], bh[nt]);
#pragma unroll
            for (int mt = 0; mt < 4; mt++)
#pragma unroll
                for (int nt = 0; nt < 4; nt++)
                    mma16816(acc[mt][nt], ah[mt], bl[nt]);
#pragma unroll
            for (int mt = 0; mt < 4; mt++)
#pragma unroll
                for (int nt = 0; nt < 4; nt++)
                    mma16816(acc[mt][nt], al[mt], bh[nt]);
        }
    }

    // Epilogue
    const int erow = m0 + wm + (lane >> 2);
    const int ecol0 = n0 + wn + (lane & 3) * 2;
    float2 brg[4];
#pragma unroll
    for (int nt = 0; nt < 4; nt++)
        brg[nt] = *(const float2*)(bias + ecol0 + nt * 8);
#pragma unroll
    for (int mt = 0; mt < 4; mt++) {
        int r0 = erow + mt * 16;
#pragma unroll
        for (int nt = 0; nt < 4; nt++) {
            float2 v0 = {acc[mt][nt][0] + brg[nt].x, acc[mt][nt][1] + brg[nt].y};
            float2 v1 = {acc[mt][nt][2] + brg[nt].x, acc[mt][nt][3] + brg[nt].y};
            *(float2*)(g_cur + (size_t)r0 * NN + ecol0 + nt * 8) = v0;
            *(float2*)(g_cur + (size_t)(r0 + 8) * NN + ecol0 + nt * 8) = v1;
        }
    }
}

// ---------------------------------------------------------------------------
// ALIF scan: 128 CTAs = 2 per batch. Both pair members compute identical
// states (compute is cheap); each writes HALF the output streams:
//   p=0: zs + v_full(+pad)     p=1: z_full + b_full (+pads)
// This spreads the store traffic over 128 SMs instead of 64.
// ---------------------------------------------------------------------------
__global__ __launch_bounds__(128) void alif_scan(const float* __restrict__ beta,
                                                 const float* __restrict__ beta2,
                                                 const float* __restrict__ decay_v,
                                                 const float* __restrict__ decay_b,
                                                 float* __restrict__ out) {
    const int b = blockIdx.x >> 1;
    const int p = blockIdx.x & 1;
    const int tid = threadIdx.x;
    const int w = tid >> 5, lane = tid & 31;

    __shared__ int wsum[4];
    __shared__ int act[NN];

    const float4 be = ((const float4*)beta)[tid];
    const float4 b2 = ((const float4*)beta2)[tid];
    const float4 dv = ((const float4*)decay_v)[tid];
    const float4 db = ((const float4*)decay_b)[tid];
    const float4 omdv = {1.f - dv.x, 1.f - dv.y, 1.f - dv.z, 1.f - dv.w};
    const float4 omdb = {1.f - db.x, 1.f - db.y, 1.f - db.z, 1.f - db.w};

    float4 v  = {0.f, 0.f, 0.f, 0.f};
    float4 bb = {0.f, 0.f, 0.f, 0.f};
    float4 zp = {0.f, 0.f, 0.f, 0.f};
    int nact = 0;

    const float4* cur4 = (const float4*)(g_cur + (size_t)b * NT * NN);
    const float4* Rt4  = (const float4*)g_Rt;

    float* zsb = out + (size_t)b * NT * NN;
    float* vf  = out + ZS_ELEMS + (size_t)(0 * NB + b) * ST_STRIDE;
    float* zf  = out + ZS_ELEMS + (size_t)(1 * NB + b) * ST_STRIDE;
    float* bf  = out + ZS_ELEMS + (size_t)(2 * NB + b) * ST_STRIDE;

    const float4 zero4 = {0.f, 0.f, 0.f, 0.f};
    if (p == 0) {
        ((float4*)vf)[tid] = zero4;
    } else {
        ((float4*)zf)[tid] = zero4;
        ((float4*)bf)[tid] = zero4;
    }

    float4 cpre[8];
#pragma unroll
    for (int i = 0; i < 8; i++) cpre[i] = cur4[(size_t)i * 128 + tid];

    for (int tb = 0; tb < NT; tb += 8) {
#pragma unroll
        for (int u = 0; u < 8; u++) {
            const int t = tb + u;
            float4 c = cpre[u];
            if (t + 8 < NT) cpre[u] = cur4[(size_t)(t + 8) * 128 + tid];

            float4 rec = {0.f, 0.f, 0.f, 0.f};
            for (int k = 0; k < nact; k++) {
                float4 r = Rt4[(size_t)act[k] * 128 + tid];
                rec.x += r.x; rec.y += r.y; rec.z += r.z; rec.w += r.w;
            }

            v.x *= (1.f - zp.x); v.y *= (1.f - zp.y); v.z *= (1.f - zp.z); v.w *= (1.f - zp.w);
            float4 vt;
            vt.x = dv.x * v.x + omdv.x * ((c.x + rec.x) - bb.x);
            vt.y = dv.y * v.y + omdv.y * ((c.y + rec.y) - bb.y);
            vt.z = dv.z * v.z + omdv.z * ((c.z + rec.z) - bb.z);
            vt.w = dv.w * v.w + omdv.w * ((c.w + rec.w) - bb.w);
            float4 zt;
            zt.x = (vt.x >= 1.0f) ? 1.f : 0.f;
            zt.y = (vt.y >= 1.0f) ? 1.f : 0.f;
            zt.z = (vt.z >= 1.0f) ? 1.f : 0.f;
            zt.w = (vt.w >= 1.0f) ? 1.f : 0.f;
            bb.x = db.x * bb.x + omdb.x * (be.x * vt.x + b2.x * zt.x);
            bb.y = db.y * bb.y + omdb.y * (be.y * vt.y + b2.y * zt.y);
            bb.z = db.z * bb.z + omdb.z * (be.z * vt.z + b2.z * zt.z);
            bb.w = db.w * bb.w + omdb.w * (be.w * vt.w + b2.w * zt.w);
            v = vt; zp = zt;

            size_t tpo = (size_t)(t + 1) * 128 + tid;
            if (p == 0) {
                ((float4*)zsb)[(size_t)t * 128 + tid] = zt;
                ((float4*)vf)[tpo] = vt;
            } else {
                ((float4*)zf)[tpo] = zt;
                ((float4*)bf)[tpo] = bb;
            }

            int any = (zt.x != 0.f) | (zt.y != 0.f) | (zt.z != 0.f) | (zt.w != 0.f);
            int flag = __syncthreads_count(any);
            if (flag) {
                int myspk = (zt.x != 0.f) + (zt.y != 0.f) + (zt.z != 0.f) + (zt.w != 0.f);
                int incl = myspk;
#pragma unroll
                for (int d = 1; d < 32; d <<= 1) {
                    int n = __shfl_up_sync(0xffffffffu, incl, d);
                    if (lane >= d) incl += n;
                }
                if (lane == 31) wsum[w] = incl;
                __syncthreads();
                int basep = 0, tot = 0;
#pragma unroll
                for (int i = 0; i < 4; i++) {
                    int sv = wsum[i];
                    if (i < w) basep += sv;
                    tot += sv;
                }
                int pos = basep + incl - myspk;
                int o0 = tid * 4;
                if (zt.x != 0.f) act[pos++] = o0 + 0;
                if (zt.y != 0.f) act[pos++] = o0 + 1;
                if (zt.z != 0.f) act[pos++] = o0 + 2;
                if (zt.w != 0.f) act[pos++] = o0 + 3;
                __syncthreads();
                nact = tot;
            } else {
                nact = 0;
            }
        }
    }
}

// ---------------------------------------------------------------------------
extern "C" void kernel_launch(void* const* d_in, const int* in_sizes, int n_in,
                              void* d_out, int out_size) {
    const float* x     = (const float*)d_in[0];
    const float* W     = (const float*)d_in[1];
    const float* bias  = (const float*)d_in[2];
    const float* R     = (const float*)d_in[3];
    const float* beta  = (const float*)d_in[4];
    const float* beta2 = (const float*)d_in[5];
    const float* dvp   = (const float*)d_in[6];
    const float* dbp   = (const float*)d_in[7];
    float* out = (float*)d_out;

    cudaFuncSetAttribute(gemm_tc, cudaFuncAttributeMaxDynamicSharedMemorySize, GEMM_SMEM);

    dim3 tgrid(NN / 32, NN / 32), tblk(32, 32);
    transpose_R<<<tgrid, tblk>>>(R);

    convert_x<<<(NM * NI / 4) / 256, 256>>>(x);
    convert_w<<<(NN * NI / 4) / 256, 256>>>(W);

    dim3 ggrid(NN / 64, NM / 128);   // (8, 500), n fastest
    gemm_tc<<<ggrid, 128, GEMM_SMEM>>>(bias);

    alif_scan<<<2 * NB, 128>>>(beta, beta2, dvp, dbp, out);
}

// round 7
// speedup vs baseline: 3.2782x; 1.3239x over previous
#include <cuda_runtime.h>
#include <cuda_bf16.h>
#include <cuda_fp16.h>
#include <cstdint>

// Problem constants
#define NB   64
#define NT   1000
#define NN   512
#define NI   512
#define NM   (NB*NT)

#define ZS_ELEMS   (NB*NT*NN)
#define ST_STRIDE  ((NT+1)*NN)

// ---------------------------------------------------------------------------
// Scratch (device globals — no allocation allowed)
// ---------------------------------------------------------------------------
__device__ float  g_cur[(size_t)NM * NN];
__device__ float  g_Rt[NN * NN];
__device__ __align__(16) __half g_xh[(size_t)NM * NI];
__device__ __align__(16) __half g_wh[NN * NI];
__device__ __align__(16) __half g_wl[NN * NI];

// ---------------------------------------------------------------------------
// Portable PTX helpers (sm_80+ only — tcgen05 unavailable at compute_103)
// ---------------------------------------------------------------------------
__device__ __forceinline__ uint32_t smem_to_u32(const void* p) {
    uint32_t a;
    asm("{ .reg .u64 t; cvta.to.shared.u64 t, %1; cvt.u32.u64 %0, t; }" : "=r"(a) : "l"(p));
    return a;
}
__device__ __forceinline__ void cp_async16(uint32_t dst, const void* src) {
    asm volatile("cp.async.cg.shared.global [%0], [%1], 16;" :: "r"(dst), "l"(src) : "memory");
}
__device__ __forceinline__ void ldsm_x4(uint32_t r[4], uint32_t addr) {
    asm volatile("ldmatrix.sync.aligned.m8n8.x4.shared.b16 {%0,%1,%2,%3}, [%4];"
        : "=r"(r[0]), "=r"(r[1]), "=r"(r[2]), "=r"(r[3]) : "r"(addr));
}
__device__ __forceinline__ void mma16816f(float d[4], const uint32_t a[4], const uint32_t b[2]) {
    asm volatile("mma.sync.aligned.m16n8k16.row.col.f32.f16.f16.f32 "
        "{%0,%1,%2,%3}, {%4,%5,%6,%7}, {%8,%9}, {%0,%1,%2,%3};"
        : "+f"(d[0]), "+f"(d[1]), "+f"(d[2]), "+f"(d[3])
        : "r"(a[0]), "r"(a[1]), "r"(a[2]), "r"(a[3]), "r"(b[0]), "r"(b[1]));
}
#define SWZ(off) ((off) ^ (((off) >> 3) & 0x70))

// ---------------------------------------------------------------------------
// R transpose
// ---------------------------------------------------------------------------
__global__ void transpose_R(const float* __restrict__ R) {
    __shared__ float tile[32][33];
    int bx = blockIdx.x * 32, by = blockIdx.y * 32;
    tile[threadIdx.y][threadIdx.x] = R[(by + threadIdx.y) * NN + bx + threadIdx.x];
    __syncthreads();
    g_Rt[(bx + threadIdx.y) * NN + (by + threadIdx.x)] = tile[threadIdx.x][threadIdx.y];
}

// ---------------------------------------------------------------------------
// Converts: x -> f16 single; w -> f16 hi + f16 lo
// ---------------------------------------------------------------------------
__global__ __launch_bounds__(256) void convert_x(const float* __restrict__ src) {
    int i = blockIdx.x * 256 + threadIdx.x;
    float4 v = ((const float4*)src)[i];
    ushort4 o;
    o.x = __half_as_ushort(__float2half_rn(v.x));
    o.y = __half_as_ushort(__float2half_rn(v.y));
    o.z = __half_as_ushort(__float2half_rn(v.z));
    o.w = __half_as_ushort(__float2half_rn(v.w));
    ((ushort4*)g_xh)[i] = o;
}
__global__ __launch_bounds__(256) void convert_w(const float* __restrict__ src) {
    int i = blockIdx.x * 256 + threadIdx.x;
    float4 v = ((const float4*)src)[i];
    __half h0 = __float2half_rn(v.x), h1 = __float2half_rn(v.y);
    __half h2 = __float2half_rn(v.z), h3 = __float2half_rn(v.w);
    ushort4 hv, lv;
    hv.x = __half_as_ushort(h0); hv.y = __half_as_ushort(h1);
    hv.z = __half_as_ushort(h2); hv.w = __half_as_ushort(h3);
    lv.x = __half_as_ushort(__float2half_rn(v.x - __half2float(h0)));
    lv.y = __half_as_ushort(__float2half_rn(v.y - __half2float(h1)));
    lv.z = __half_as_ushort(__float2half_rn(v.z - __half2float(h2)));
    lv.w = __half_as_ushort(__float2half_rn(v.w - __half2float(h3)));
    ((ushort4*)g_wh)[i] = hv;
    ((ushort4*)g_wl)[i] = lv;
}

// ---------------------------------------------------------------------------
// f16 2-pass GEMM via mma.sync: cur = Xh*(Wh + Wl) + bias.
// CTA 128x64 tile, 4 warps (2m x 2n), warp tile 64x32, BK=64, 3 stages.
// Stage (32KB): 256 rows x 128B; rows 0-127 = A(xh), 128-191 = Wh, 192-255 = Wl.
// ---------------------------------------------------------------------------
#define BK       64
#define NCHUNK   (NI / BK)       // 8
#define NSTAGE   3
#define STAGE_B  (256 * 128)     // 32768
#define GEMM_SMEM (NSTAGE * STAGE_B)   // 98304

__global__ __launch_bounds__(128, 2) void gemm_tc(const float* __restrict__ bias) {
    extern __shared__ char smem[];
    uint32_t sb = smem_to_u32(smem);
    const int tid = threadIdx.x, lane = tid & 31, wid = tid >> 5;
    const int m0 = blockIdx.y * 128, n0 = blockIdx.x * 64;
    const int wm = (wid & 1) * 64;
    const int wn = (wid >> 1) * 32;

    float acc[4][4][4];
#pragma unroll
    for (int i = 0; i < 4; i++)
#pragma unroll
        for (int j = 0; j < 4; j++)
#pragma unroll
            for (int k = 0; k < 4; k++) acc[i][j][k] = 0.f;

    // loader: thread t owns A row t (xh) and B row 128+t (t<64: Wh row n0+t;
    // t>=64: Wl row n0+t-64 -> smem row 192+(t-64) = 128+t).
    const __half* pA = g_xh + (size_t)(m0 + tid) * NI;
    const __half* pB = (tid < 64) ? (g_wh + (size_t)(n0 + tid) * NI)
                                  : (g_wl + (size_t)(n0 + tid - 64) * NI);
    const uint32_t rowA = (uint32_t)tid * 128;
    const uint32_t rowB = (uint32_t)(128 + tid) * 128;

    auto load_chunk = [&](int c) {
        uint32_t base = sb + (uint32_t)(c % NSTAGE) * STAGE_B;
#pragma unroll
        for (int j = 0; j < 8; j++)
            cp_async16(base + SWZ(rowA + j * 16), pA + c * BK + j * 8);
#pragma unroll
        for (int j = 0; j < 8; j++)
            cp_async16(base + SWZ(rowB + j * 16), pB + c * BK + j * 8);
        asm volatile("cp.async.commit_group;" ::: "memory");
    };

    const int a_row = wm + (lane & 15);
    const int a_cb  = (lane >> 4) * 16;
    const int b_row = 128 + wn + (lane & 7) + ((lane >> 4) * 8);
    const int b_cb  = ((lane >> 3) & 1) * 16;

    load_chunk(0);
    load_chunk(1);

    for (int c = 0; c < NCHUNK; c++) {
        asm volatile("cp.async.wait_group %0;" :: "n"(NSTAGE - 2) : "memory");
        __syncthreads();

        if (c + NSTAGE - 1 < NCHUNK) {
            load_chunk(c + NSTAGE - 1);
        } else {
            asm volatile("cp.async.commit_group;" ::: "memory");
        }

        uint32_t base = sb + (uint32_t)(c % NSTAGE) * STAGE_B;
#pragma unroll
        for (int kk = 0; kk < 4; kk++) {   // 4 x k16 within BK=64
            uint32_t ah[4][4], bh[4][2], bl[4][2];
#pragma unroll
            for (int mt = 0; mt < 4; mt++) {
                uint32_t off = (uint32_t)((a_row + mt * 16) * 128 + kk * 32 + a_cb);
                ldsm_x4(ah[mt], base + SWZ(off));
            }
#pragma unroll
            for (int p = 0; p < 2; p++) {
                uint32_t off = (uint32_t)((b_row + p * 16) * 128 + kk * 32 + b_cb);
                uint32_t t4[4];
                ldsm_x4(t4, base + SWZ(off));
                bh[2 * p][0] = t4[0]; bh[2 * p][1] = t4[1];
                bh[2 * p + 1][0] = t4[2]; bh[2 * p + 1][1] = t4[3];
                ldsm_x4(t4, base + SWZ(off + 64 * 128));   // Wl rows are +64
                bl[2 * p][0] = t4[0]; bl[2 * p][1] = t4[1];
                bl[2 * p + 1][0] = t4[2]; bl[2 * p + 1][1] = t4[3];
            }
            // pass-major: consecutive MMAs hit different accumulators
#pragma unroll
            for (int mt = 0; mt < 4; mt++)
#pragma unroll
                for (int nt = 0; nt < 4; nt++)
                    mma16816f(acc[mt][nt], ah[mt], bh[nt]);
#pragma unroll
            for (int mt = 0; mt < 4; mt++)
#pragma unroll
                for (int nt = 0; nt < 4; nt++)
                    mma16816f(acc[mt][nt], ah[mt], bl[nt]);
        }
    }

    // Epilogue
    const int erow = m0 + wm + (lane >> 2);
    const int ecol0 = n0 + wn + (lane & 3) * 2;
    float2 brg[4];
#pragma unroll
    for (int nt = 0; nt < 4; nt++)
        brg[nt] = *(const float2*)(bias + ecol0 + nt * 8);
#pragma unroll
    for (int mt = 0; mt < 4; mt++) {
        int r0 = erow + mt * 16;
#pragma unroll
        for (int nt = 0; nt < 4; nt++) {
            float2 v0 = {acc[mt][nt][0] + brg[nt].x, acc[mt][nt][1] + brg[nt].y};
            float2 v1 = {acc[mt][nt][2] + brg[nt].x, acc[mt][nt][3] + brg[nt].y};
            *(float2*)(g_cur + (size_t)r0 * NN + ecol0 + nt * 8) = v0;
            *(float2*)(g_cur + (size_t)(r0 + 8) * NN + ecol0 + nt * 8) = v1;
        }
    }
}

// ---------------------------------------------------------------------------
// ALIF scan with speculation: 8-step windows run barrier-free assuming no
// spikes; one __syncthreads_count per window verifies. On a spike (rare /
// never for this data) roll back registers and redo the window with the full
// per-step ballot + recurrent-gather path. 2 CTAs per batch split the output
// streams (p0: zs + v_full, p1: z_full + b_full).
// ---------------------------------------------------------------------------
__global__ __launch_bounds__(128) void alif_scan(const float* __restrict__ beta,
                                                 const float* __restrict__ beta2,
                                                 const float* __restrict__ decay_v,
                                                 const float* __restrict__ decay_b,
                                                 float* __restrict__ out) {
    const int b = blockIdx.x >> 1;
    const int p = blockIdx.x & 1;
    const int tid = threadIdx.x;
    const int w = tid >> 5, lane = tid & 31;

    __shared__ int wsum[4];
    __shared__ int act[NN];

    const float4 be = ((const float4*)beta)[tid];
    const float4 b2 = ((const float4*)beta2)[tid];
    const float4 dv = ((const float4*)decay_v)[tid];
    const float4 db = ((const float4*)decay_b)[tid];
    const float4 omdv = {1.f - dv.x, 1.f - dv.y, 1.f - dv.z, 1.f - dv.w};
    const float4 omdb = {1.f - db.x, 1.f - db.y, 1.f - db.z, 1.f - db.w};

    float4 v  = {0.f, 0.f, 0.f, 0.f};
    float4 bb = {0.f, 0.f, 0.f, 0.f};
    float4 zp = {0.f, 0.f, 0.f, 0.f};
    int nact = 0;

    const float4* cur4 = (const float4*)(g_cur + (size_t)b * NT * NN);
    const float4* Rt4  = (const float4*)g_Rt;

    float* zsb = out + (size_t)b * NT * NN;
    float* vf  = out + ZS_ELEMS + (size_t)(0 * NB + b) * ST_STRIDE;
    float* zf  = out + ZS_ELEMS + (size_t)(1 * NB + b) * ST_STRIDE;
    float* bf  = out + ZS_ELEMS + (size_t)(2 * NB + b) * ST_STRIDE;

    const float4 zero4 = {0.f, 0.f, 0.f, 0.f};
    if (p == 0) {
        ((float4*)vf)[tid] = zero4;
    } else {
        ((float4*)zf)[tid] = zero4;
        ((float4*)bf)[tid] = zero4;
    }

    float4 cpre[8];
#pragma unroll
    for (int i = 0; i < 8; i++) cpre[i] = cur4[(size_t)i * 128 + tid];

    // Full-accuracy window (per-step sync + spike compaction); used when
    // spikes exist or speculation failed. Loads c fresh from global and
    // refills the prefetch ring at the end to restore the window invariant.
    auto slow_window = [&](int tb) {
        for (int u = 0; u < 8; u++) {
            const int t = tb + u;
            float4 c = cur4[(size_t)t * 128 + tid];

            float4 rec = {0.f, 0.f, 0.f, 0.f};
            for (int k = 0; k < nact; k++) {
                float4 r = Rt4[(size_t)act[k] * 128 + tid];
                rec.x += r.x; rec.y += r.y; rec.z += r.z; rec.w += r.w;
            }

            v.x *= (1.f - zp.x); v.y *= (1.f - zp.y); v.z *= (1.f - zp.z); v.w *= (1.f - zp.w);
            float4 vt;
            vt.x = dv.x * v.x + omdv.x * ((c.x + rec.x) - bb.x);
            vt.y = dv.y * v.y + omdv.y * ((c.y + rec.y) - bb.y);
            vt.z = dv.z * v.z + omdv.z * ((c.z + rec.z) - bb.z);
            vt.w = dv.w * v.w + omdv.w * ((c.w + rec.w) - bb.w);
            float4 zt;
            zt.x = (vt.x >= 1.0f) ? 1.f : 0.f;
            zt.y = (vt.y >= 1.0f) ? 1.f : 0.f;
            zt.z = (vt.z >= 1.0f) ? 1.f : 0.f;
            zt.w = (vt.w >= 1.0f) ? 1.f : 0.f;
            bb.x = db.x * bb.x + omdb.x * (be.x * vt.x + b2.x * zt.x);
            bb.y = db.y * bb.y + omdb.y * (be.y * vt.y + b2.y * zt.y);
            bb.z = db.z * bb.z + omdb.z * (be.z * vt.z + b2.z * zt.z);
            bb.w = db.w * bb.w + omdb.w * (be.w * vt.w + b2.w * zt.w);
            v = vt; zp = zt;

            size_t tpo = (size_t)(t + 1) * 128 + tid;
            if (p == 0) {
                ((float4*)zsb)[(size_t)t * 128 + tid] = zt;
                ((float4*)vf)[tpo] = vt;
            } else {
                ((float4*)zf)[tpo] = zt;
                ((float4*)bf)[tpo] = bb;
            }

            int any = (zt.x != 0.f) | (zt.y != 0.f) | (zt.z != 0.f) | (zt.w != 0.f);
            int flag = __syncthreads_count(any);
            if (flag) {
                int myspk = (zt.x != 0.f) + (zt.y != 0.f) + (zt.z != 0.f) + (zt.w != 0.f);
                int incl = myspk;
#pragma unroll
                for (int d = 1; d < 32; d <<= 1) {
                    int n = __shfl_up_sync(0xffffffffu, incl, d);
                    if (lane >= d) incl += n;
                }
                if (lane == 31) wsum[w] = incl;
                __syncthreads();
                int basep = 0, tot = 0;
#pragma unroll
                for (int i = 0; i < 4; i++) {
                    int sv = wsum[i];
                    if (i < w) basep += sv;
                    tot += sv;
                }
                int pos = basep + incl - myspk;
                int o0 = tid * 4;
                if (zt.x != 0.f) act[pos++] = o0 + 0;
                if (zt.y != 0.f) act[pos++] = o0 + 1;
                if (zt.z != 0.f) act[pos++] = o0 + 2;
                if (zt.w != 0.f) act[pos++] = o0 + 3;
                __syncthreads();
                nact = tot;
            } else {
                nact = 0;
            }
        }
        // restore prefetch-ring invariant for the next window
#pragma unroll
        for (int u = 0; u < 8; u++) {
            int tp = tb + 8 + u;
            if (tp < NT) cpre[u] = cur4[(size_t)tp * 128 + tid];
        }
    };

    for (int tb = 0; tb < NT; tb += 8) {
        if (nact == 0) {
            // speculative fast path: no spikes assumed, no per-step barriers.
            // nact==0 implies zp==0 for every thread.
            const float4 v0 = v, bb0 = bb;
            int spec = 0;
#pragma unroll
            for (int u = 0; u < 8; u++) {
                const int t = tb + u;
                float4 c = cpre[u];
                if (t + 8 < NT) cpre[u] = cur4[(size_t)(t + 8) * 128 + tid];

                float4 vt;
                vt.x = dv.x * v.x + omdv.x * (c.x - bb.x);
                vt.y = dv.y * v.y + omdv.y * (c.y - bb.y);
                vt.z = dv.z * v.z + omdv.z * (c.z - bb.z);
                vt.w = dv.w * v.w + omdv.w * (c.w - bb.w);
                float4 zt;
                zt.x = (vt.x >= 1.0f) ? 1.f : 0.f;
                zt.y = (vt.y >= 1.0f) ? 1.f : 0.f;
                zt.z = (vt.z >= 1.0f) ? 1.f : 0.f;
                zt.w = (vt.w >= 1.0f) ? 1.f : 0.f;
                spec |= (zt.x != 0.f) | (zt.y != 0.f) | (zt.z != 0.f) | (zt.w != 0.f);
                bb.x = db.x * bb.x + omdb.x * (be.x * vt.x + b2.x * zt.x);
                bb.y = db.y * bb.y + omdb.y * (be.y * vt.y + b2.y * zt.y);
                bb.z = db.z * bb.z + omdb.z * (be.z * vt.z + b2.z * zt.z);
                bb.w = db.w * bb.w + omdb.w * (be.w * vt.w + b2.w * zt.w);
                v = vt;

                size_t tpo = (size_t)(t + 1) * 128 + tid;
                if (p == 0) {
                    ((float4*)zsb)[(size_t)t * 128 + tid] = zt;
                    ((float4*)vf)[tpo] = vt;
                } else {
                    ((float4*)zf)[tpo] = zt;
                    ((float4*)bf)[tpo] = bb;
                }
            }
            int flag = __syncthreads_count(spec);
            if (flag) {
                // speculation failed: roll back and redo with full path
                v = v0; bb = bb0; zp = zero4; nact = 0;
                slow_window(tb);
            } else {
                zp = zero4; nact = 0;
            }
        } else {
            slow_window(tb);
        }
    }
}

// ---------------------------------------------------------------------------
extern "C" void kernel_launch(void* const* d_in, const int* in_sizes, int n_in,
                              void* d_out, int out_size) {
    const float* x     = (const float*)d_in[0];
    const float* W     = (const float*)d_in[1];
    const float* bias  = (const float*)d_in[2];
    const float* R     = (const float*)d_in[3];
    const float* beta  = (const float*)d_in[4];
    const float* beta2 = (const float*)d_in[5];
    const float* dvp   = (const float*)d_in[6];
    const float* dbp   = (const float*)d_in[7];
    float* out = (float*)d_out;

    cudaFuncSetAttribute(gemm_tc, cudaFuncAttributeMaxDynamicSharedMemorySize, GEMM_SMEM);

    dim3 tgrid(NN / 32, NN / 32), tblk(32, 32);
    transpose_R<<<tgrid, tblk>>>(R);

    convert_x<<<(NM * NI / 4) / 256, 256>>>(x);
    convert_w<<<(NN * NI / 4) / 256, 256>>>(W);

    dim3 ggrid(NN / 64, NM / 128);   // (8, 500), n fastest
    gemm_tc<<<ggrid, 128, GEMM_SMEM>>>(bias);

    alif_scan<<<2 * NB, 128>>>(beta, beta2, dvp, dbp, out);
}

// round 8
// speedup vs baseline: 4.1898x; 1.2781x over previous
#include <cuda_runtime.h>
#include <cuda_bf16.h>
#include <cuda_fp16.h>
#include <cstdint>

// Problem constants
#define NB   64
#define NT   1000
#define NN   512
#define NI   512
#define NM   (NB*NT)

#define ZS_ELEMS   (NB*NT*NN)
#define ST_STRIDE  ((NT+1)*NN)

// ---------------------------------------------------------------------------
// Scratch (device globals — no allocation allowed)
// ---------------------------------------------------------------------------
__device__ float  g_cur[(size_t)NM * NN];
__device__ float  g_Rt[NN * NN];
__device__ __align__(16) __half g_xh[(size_t)NM * NI];
__device__ __align__(16) __half g_wh[NN * NI];

// ---------------------------------------------------------------------------
// Portable PTX helpers (sm_80+ only — tcgen05 unavailable at compute_103)
// ---------------------------------------------------------------------------
__device__ __forceinline__ uint32_t smem_to_u32(const void* p) {
    uint32_t a;
    asm("{ .reg .u64 t; cvta.to.shared.u64 t, %1; cvt.u32.u64 %0, t; }" : "=r"(a) : "l"(p));
    return a;
}
__device__ __forceinline__ void cp_async16(uint32_t dst, const void* src) {
    asm volatile("cp.async.cg.shared.global [%0], [%1], 16;" :: "r"(dst), "l"(src) : "memory");
}
__device__ __forceinline__ void ldsm_x4(uint32_t r[4], uint32_t addr) {
    asm volatile("ldmatrix.sync.aligned.m8n8.x4.shared.b16 {%0,%1,%2,%3}, [%4];"
        : "=r"(r[0]), "=r"(r[1]), "=r"(r[2]), "=r"(r[3]) : "r"(addr));
}
__device__ __forceinline__ void mma16816f(float d[4], const uint32_t a[4], const uint32_t b[2]) {
    asm volatile("mma.sync.aligned.m16n8k16.row.col.f32.f16.f16.f32 "
        "{%0,%1,%2,%3}, {%4,%5,%6,%7}, {%8,%9}, {%0,%1,%2,%3};"
        : "+f"(d[0]), "+f"(d[1]), "+f"(d[2]), "+f"(d[3])
        : "r"(a[0]), "r"(a[1]), "r"(a[2]), "r"(a[3]), "r"(b[0]), "r"(b[1]));
}
#define SWZ(off) ((off) ^ (((off) >> 3) & 0x70))

// ---------------------------------------------------------------------------
// R transpose
// ---------------------------------------------------------------------------
__global__ void transpose_R(const float* __restrict__ R) {
    __shared__ float tile[32][33];
    int bx = blockIdx.x * 32, by = blockIdx.y * 32;
    tile[threadIdx.y][threadIdx.x] = R[(by + threadIdx.y) * NN + bx + threadIdx.x];
    __syncthreads();
    g_Rt[(bx + threadIdx.y) * NN + (by + threadIdx.x)] = tile[threadIdx.x][threadIdx.y];
}

// ---------------------------------------------------------------------------
// Converts: x -> f16, w -> f16 (single precision pass each)
// ---------------------------------------------------------------------------
__global__ __launch_bounds__(256) void convert_x(const float* __restrict__ src) {
    int i = blockIdx.x * 256 + threadIdx.x;
    float4 v = ((const float4*)src)[i];
    ushort4 o;
    o.x = __half_as_ushort(__float2half_rn(v.x));
    o.y = __half_as_ushort(__float2half_rn(v.y));
    o.z = __half_as_ushort(__float2half_rn(v.z));
    o.w = __half_as_ushort(__float2half_rn(v.w));
    ((ushort4*)g_xh)[i] = o;
}
__global__ __launch_bounds__(256) void convert_w(const float* __restrict__ src) {
    int i = blockIdx.x * 256 + threadIdx.x;
    float4 v = ((const float4*)src)[i];
    ushort4 o;
    o.x = __half_as_ushort(__float2half_rn(v.x));
    o.y = __half_as_ushort(__float2half_rn(v.y));
    o.z = __half_as_ushort(__float2half_rn(v.z));
    o.w = __half_as_ushort(__float2half_rn(v.w));
    ((ushort4*)g_wh)[i] = o;
}

// ---------------------------------------------------------------------------
// f16 1-pass GEMM via mma.sync: cur = Xh*Wh + bias.
// CTA 128x64 tile, 4 warps (2m x 2n), warp tile 64x32, BK=64, 3 stages.
// Stage (24KB): 192 rows x 128B; rows 0-127 = A(xh), 128-191 = Wh.
// 72KB smem + ~130 regs -> 3 CTAs/SM for latency cover.
// ---------------------------------------------------------------------------
#define BK       64
#define NCHUNK   (NI / BK)       // 8
#define NSTAGE   3
#define STAGE_B  (192 * 128)     // 24576
#define GEMM_SMEM (NSTAGE * STAGE_B)   // 73728

__global__ __launch_bounds__(128, 3) void gemm_tc(const float* __restrict__ bias) {
    extern __shared__ char smem[];
    uint32_t sb = smem_to_u32(smem);
    const int tid = threadIdx.x, lane = tid & 31, wid = tid >> 5;
    const int m0 = blockIdx.y * 128, n0 = blockIdx.x * 64;
    const int wm = (wid & 1) * 64;
    const int wn = (wid >> 1) * 32;

    float acc[4][4][4];
#pragma unroll
    for (int i = 0; i < 4; i++)
#pragma unroll
        for (int j = 0; j < 4; j++)
#pragma unroll
            for (int k = 0; k < 4; k++) acc[i][j][k] = 0.f;

    // loader: thread t owns A row t; threads 0-63 additionally own B row 128+t
    const __half* pA = g_xh + (size_t)(m0 + tid) * NI;
    const bool hasB = (tid < 64);
    const __half* pB = g_wh + (size_t)(n0 + (tid & 63)) * NI;
    const uint32_t rowA = (uint32_t)tid * 128;
    const uint32_t rowB = (uint32_t)(128 + tid) * 128;

    auto load_chunk = [&](int c) {
        uint32_t base = sb + (uint32_t)(c % NSTAGE) * STAGE_B;
#pragma unroll
        for (int j = 0; j < 8; j++)
            cp_async16(base + SWZ(rowA + j * 16), pA + c * BK + j * 8);
        if (hasB) {
#pragma unroll
            for (int j = 0; j < 8; j++)
                cp_async16(base + SWZ(rowB + j * 16), pB + c * BK + j * 8);
        }
        asm volatile("cp.async.commit_group;" ::: "memory");
    };

    const int a_row = wm + (lane & 15);
    const int a_cb  = (lane >> 4) * 16;
    const int b_row = 128 + wn + (lane & 7) + ((lane >> 4) * 8);
    const int b_cb  = ((lane >> 3) & 1) * 16;

    load_chunk(0);
    load_chunk(1);

    for (int c = 0; c < NCHUNK; c++) {
        asm volatile("cp.async.wait_group %0;" :: "n"(NSTAGE - 2) : "memory");
        __syncthreads();

        if (c + NSTAGE - 1 < NCHUNK) {
            load_chunk(c + NSTAGE - 1);
        } else {
            asm volatile("cp.async.commit_group;" ::: "memory");
        }

        uint32_t base = sb + (uint32_t)(c % NSTAGE) * STAGE_B;
#pragma unroll
        for (int kk = 0; kk < 4; kk++) {   // 4 x k16 within BK=64
            uint32_t ah[4][4], bh[4][2];
#pragma unroll
            for (int mt = 0; mt < 4; mt++) {
                uint32_t off = (uint32_t)((a_row + mt * 16) * 128 + kk * 32 + a_cb);
                ldsm_x4(ah[mt], base + SWZ(off));
            }
#pragma unroll
            for (int p = 0; p < 2; p++) {
                uint32_t off = (uint32_t)((b_row + p * 16) * 128 + kk * 32 + b_cb);
                uint32_t t4[4];
                ldsm_x4(t4, base + SWZ(off));
                bh[2 * p][0] = t4[0]; bh[2 * p][1] = t4[1];
                bh[2 * p + 1][0] = t4[2]; bh[2 * p + 1][1] = t4[3];
            }
            // pass-major: consecutive MMAs hit different accumulators
#pragma unroll
            for (int mt = 0; mt < 4; mt++)
#pragma unroll
                for (int nt = 0; nt < 4; nt++)
                    mma16816f(acc[mt][nt], ah[mt], bh[nt]);
        }
    }

    // Epilogue
    const int erow = m0 + wm + (lane >> 2);
    const int ecol0 = n0 + wn + (lane & 3) * 2;
    float2 brg[4];
#pragma unroll
    for (int nt = 0; nt < 4; nt++)
        brg[nt] = *(const float2*)(bias + ecol0 + nt * 8);
#pragma unroll
    for (int mt = 0; mt < 4; mt++) {
        int r0 = erow + mt * 16;
#pragma unroll
        for (int nt = 0; nt < 4; nt++) {
            float2 v0 = {acc[mt][nt][0] + brg[nt].x, acc[mt][nt][1] + brg[nt].y};
            float2 v1 = {acc[mt][nt][2] + brg[nt].x, acc[mt][nt][3] + brg[nt].y};
            *(float2*)(g_cur + (size_t)r0 * NN + ecol0 + nt * 8) = v0;
            *(float2*)(g_cur + (size_t)(r0 + 8) * NN + ecol0 + nt * 8) = v1;
        }
    }
}

// ---------------------------------------------------------------------------
// ALIF scan with speculation: 8-step windows run barrier-free assuming no
// spikes; one __syncthreads_count per window verifies. On a spike, roll back
// registers and redo the window with the full per-step ballot path.
// 2 CTAs per batch split the output streams (p0: zs + v_full, p1: z + b).
// ---------------------------------------------------------------------------
__global__ __launch_bounds__(128) void alif_scan(const float* __restrict__ beta,
                                                 const float* __restrict__ beta2,
                                                 const float* __restrict__ decay_v,
                                                 const float* __restrict__ decay_b,
                                                 float* __restrict__ out) {
    const int b = blockIdx.x >> 1;
    const int p = blockIdx.x & 1;
    const int tid = threadIdx.x;
    const int w = tid >> 5, lane = tid & 31;

    __shared__ int wsum[4];
    __shared__ int act[NN];

    const float4 be = ((const float4*)beta)[tid];
    const float4 b2 = ((const float4*)beta2)[tid];
    const float4 dv = ((const float4*)decay_v)[tid];
    const float4 db = ((const float4*)decay_b)[tid];
    const float4 omdv = {1.f - dv.x, 1.f - dv.y, 1.f - dv.z, 1.f - dv.w};
    const float4 omdb = {1.f - db.x, 1.f - db.y, 1.f - db.z, 1.f - db.w};

    float4 v  = {0.f, 0.f, 0.f, 0.f};
    float4 bb = {0.f, 0.f, 0.f, 0.f};
    float4 zp = {0.f, 0.f, 0.f, 0.f};
    int nact = 0;

    const float4* cur4 = (const float4*)(g_cur + (size_t)b * NT * NN);
    const float4* Rt4  = (const float4*)g_Rt;

    float* zsb = out + (size_t)b * NT * NN;
    float* vf  = out + ZS_ELEMS + (size_t)(0 * NB + b) * ST_STRIDE;
    float* zf  = out + ZS_ELEMS + (size_t)(1 * NB + b) * ST_STRIDE;
    float* bf  = out + ZS_ELEMS + (size_t)(2 * NB + b) * ST_STRIDE;

    const float4 zero4 = {0.f, 0.f, 0.f, 0.f};
    if (p == 0) {
        ((float4*)vf)[tid] = zero4;
    } else {
        ((float4*)zf)[tid] = zero4;
        ((float4*)bf)[tid] = zero4;
    }

    float4 cpre[8];
#pragma unroll
    for (int i = 0; i < 8; i++) cpre[i] = cur4[(size_t)i * 128 + tid];

    auto slow_window = [&](int tb) {
        for (int u = 0; u < 8; u++) {
            const int t = tb + u;
            float4 c = cur4[(size_t)t * 128 + tid];

            float4 rec = {0.f, 0.f, 0.f, 0.f};
            for (int k = 0; k < nact; k++) {
                float4 r = Rt4[(size_t)act[k] * 128 + tid];
                rec.x += r.x; rec.y += r.y; rec.z += r.z; rec.w += r.w;
            }

            v.x *= (1.f - zp.x); v.y *= (1.f - zp.y); v.z *= (1.f - zp.z); v.w *= (1.f - zp.w);
            float4 vt;
            vt.x = dv.x * v.x + omdv.x * ((c.x + rec.x) - bb.x);
            vt.y = dv.y * v.y + omdv.y * ((c.y + rec.y) - bb.y);
            vt.z = dv.z * v.z + omdv.z * ((c.z + rec.z) - bb.z);
            vt.w = dv.w * v.w + omdv.w * ((c.w + rec.w) - bb.w);
            float4 zt;
            zt.x = (vt.x >= 1.0f) ? 1.f : 0.f;
            zt.y = (vt.y >= 1.0f) ? 1.f : 0.f;
            zt.z = (vt.z >= 1.0f) ? 1.f : 0.f;
            zt.w = (vt.w >= 1.0f) ? 1.f : 0.f;
            bb.x = db.x * bb.x + omdb.x * (be.x * vt.x + b2.x * zt.x);
            bb.y = db.y * bb.y + omdb.y * (be.y * vt.y + b2.y * zt.y);
            bb.z = db.z * bb.z + omdb.z * (be.z * vt.z + b2.z * zt.z);
            bb.w = db.w * bb.w + omdb.w * (be.w * vt.w + b2.w * zt.w);
            v = vt; zp = zt;

            size_t tpo = (size_t)(t + 1) * 128 + tid;
            if (p == 0) {
                ((float4*)zsb)[(size_t)t * 128 + tid] = zt;
                ((float4*)vf)[tpo] = vt;
            } else {
                ((float4*)zf)[tpo] = zt;
                ((float4*)bf)[tpo] = bb;
            }

            int any = (zt.x != 0.f) | (zt.y != 0.f) | (zt.z != 0.f) | (zt.w != 0.f);
            int flag = __syncthreads_count(any);
            if (flag) {
                int myspk = (zt.x != 0.f) + (zt.y != 0.f) + (zt.z != 0.f) + (zt.w != 0.f);
                int incl = myspk;
#pragma unroll
                for (int d = 1; d < 32; d <<= 1) {
                    int n = __shfl_up_sync(0xffffffffu, incl, d);
                    if (lane >= d) incl += n;
                }
                if (lane == 31) wsum[w] = incl;
                __syncthreads();
                int basep = 0, tot = 0;
#pragma unroll
                for (int i = 0; i < 4; i++) {
                    int sv = wsum[i];
                    if (i < w) basep += sv;
                    tot += sv;
                }
                int pos = basep + incl - myspk;
                int o0 = tid * 4;
                if (zt.x != 0.f) act[pos++] = o0 + 0;
                if (zt.y != 0.f) act[pos++] = o0 + 1;
                if (zt.z != 0.f) act[pos++] = o0 + 2;
                if (zt.w != 0.f) act[pos++] = o0 + 3;
                __syncthreads();
                nact = tot;
            } else {
                nact = 0;
            }
        }
#pragma unroll
        for (int u = 0; u < 8; u++) {
            int tp = tb + 8 + u;
            if (tp < NT) cpre[u] = cur4[(size_t)tp * 128 + tid];
        }
    };

    for (int tb = 0; tb < NT; tb += 8) {
        if (nact == 0) {
            const float4 v0 = v, bb0 = bb;
            int spec = 0;
#pragma unroll
            for (int u = 0; u < 8; u++) {
                const int t = tb + u;
                float4 c = cpre[u];
                if (t + 8 < NT) cpre[u] = cur4[(size_t)(t + 8) * 128 + tid];

                float4 vt;
                vt.x = dv.x * v.x + omdv.x * (c.x - bb.x);
                vt.y = dv.y * v.y + omdv.y * (c.y - bb.y);
                vt.z = dv.z * v.z + omdv.z * (c.z - bb.z);
                vt.w = dv.w * v.w + omdv.w * (c.w - bb.w);
                float4 zt;
                zt.x = (vt.x >= 1.0f) ? 1.f : 0.f;
                zt.y = (vt.y >= 1.0f) ? 1.f : 0.f;
                zt.z = (vt.z >= 1.0f) ? 1.f : 0.f;
                zt.w = (vt.w >= 1.0f) ? 1.f : 0.f;
                spec |= (zt.x != 0.f) | (zt.y != 0.f) | (zt.z != 0.f) | (zt.w != 0.f);
                bb.x = db.x * bb.x + omdb.x * (be.x * vt.x + b2.x * zt.x);
                bb.y = db.y * bb.y + omdb.y * (be.y * vt.y + b2.y * zt.y);
                bb.z = db.z * bb.z + omdb.z * (be.z * vt.z + b2.z * zt.z);
                bb.w = db.w * bb.w + omdb.w * (be.w * vt.w + b2.w * zt.w);
                v = vt;

                size_t tpo = (size_t)(t + 1) * 128 + tid;
                if (p == 0) {
                    ((float4*)zsb)[(size_t)t * 128 + tid] = zt;
                    ((float4*)vf)[tpo] = vt;
                } else {
                    ((float4*)zf)[tpo] = zt;
                    ((float4*)bf)[tpo] = bb;
                }
            }
            int flag = __syncthreads_count(spec);
            if (flag) {
                v = v0; bb = bb0; zp = zero4; nact = 0;
                slow_window(tb);
            } else {
                zp = zero4; nact = 0;
            }
        } else {
            slow_window(tb);
        }
    }
}

// ---------------------------------------------------------------------------
extern "C" void kernel_launch(void* const* d_in, const int* in_sizes, int n_in,
                              void* d_out, int out_size) {
    const float* x     = (const float*)d_in[0];
    const float* W     = (const float*)d_in[1];
    const float* bias  = (const float*)d_in[2];
    const float* R     = (const float*)d_in[3];
    const float* beta  = (const float*)d_in[4];
    const float* beta2 = (const float*)d_in[5];
    const float* dvp   = (const float*)d_in[6];
    const float* dbp   = (const float*)d_in[7];
    float* out = (float*)d_out;

    cudaFuncSetAttribute(gemm_tc, cudaFuncAttributeMaxDynamicSharedMemorySize, GEMM_SMEM);

    dim3 tgrid(NN / 32, NN / 32), tblk(32, 32);
    transpose_R<<<tgrid, tblk>>>(R);

    convert_x<<<(NM * NI / 4) / 256, 256>>>(x);
    convert_w<<<(NN * NI / 4) / 256, 256>>>(W);

    dim3 ggrid(NN / 64, NM / 128);   // (8, 500), n fastest
    gemm_tc<<<ggrid, 128, GEMM_SMEM>>>(bias);

    alif_scan<<<2 * NB, 128>>>(beta, beta2, dvp, dbp, out);
}

// round 9
// speedup vs baseline: 4.3665x; 1.0422x over previous
#include <cuda_runtime.h>
#include <cuda_bf16.h>
#include <cuda_fp16.h>
#include <cstdint>

// Problem constants
#define NB   64
#define NT   1000
#define NN   512
#define NI   512
#define NM   (NB*NT)

#define ZS_ELEMS   (NB*NT*NN)
#define ST_STRIDE  ((NT+1)*NN)

// ---------------------------------------------------------------------------
// Scratch (device globals — no allocation allowed)
// ---------------------------------------------------------------------------
__device__ __align__(16) __half g_curh[(size_t)NM * NN];   // cur in f16
__device__ float  g_Rt[NN * NN];
__device__ __align__(16) __half g_xh[(size_t)NM * NI];
__device__ __align__(16) __half g_wh[NN * NI];

// ---------------------------------------------------------------------------
// Portable PTX helpers (sm_80+ only — tcgen05 unavailable at compute_103)
// ---------------------------------------------------------------------------
__device__ __forceinline__ uint32_t smem_to_u32(const void* p) {
    uint32_t a;
    asm("{ .reg .u64 t; cvta.to.shared.u64 t, %1; cvt.u32.u64 %0, t; }" : "=r"(a) : "l"(p));
    return a;
}
__device__ __forceinline__ void cp_async16(uint32_t dst, const void* src) {
    asm volatile("cp.async.cg.shared.global [%0], [%1], 16;" :: "r"(dst), "l"(src) : "memory");
}
__device__ __forceinline__ void ldsm_x4(uint32_t r[4], uint32_t addr) {
    asm volatile("ldmatrix.sync.aligned.m8n8.x4.shared.b16 {%0,%1,%2,%3}, [%4];"
        : "=r"(r[0]), "=r"(r[1]), "=r"(r[2]), "=r"(r[3]) : "r"(addr));
}
__device__ __forceinline__ void mma16816f(float d[4], const uint32_t a[4], const uint32_t b[2]) {
    asm volatile("mma.sync.aligned.m16n8k16.row.col.f32.f16.f16.f32 "
        "{%0,%1,%2,%3}, {%4,%5,%6,%7}, {%8,%9}, {%0,%1,%2,%3};"
        : "+f"(d[0]), "+f"(d[1]), "+f"(d[2]), "+f"(d[3])
        : "r"(a[0]), "r"(a[1]), "r"(a[2]), "r"(a[3]), "r"(b[0]), "r"(b[1]));
}
#define SWZ(off) ((off) ^ (((off) >> 3) & 0x70))

// ---------------------------------------------------------------------------
// prep_w: blocks 0-255 transpose R (32x32 tile each, 256 threads, 4 row-steps);
// blocks 256+ convert w -> f16.
// ---------------------------------------------------------------------------
#define TR_BLOCKS 256   // (NN/32)^2
__global__ __launch_bounds__(256) void prep_w(const float* __restrict__ R,
                                              const float* __restrict__ W) {
    int blk = blockIdx.x;
    if (blk < TR_BLOCKS) {
        __shared__ float tile[32][33];
        int bx = (blk & 15) * 32, by = (blk >> 4) * 32;
        int tx = threadIdx.x & 31, ty4 = threadIdx.x >> 5;  // 8 rows per pass
#pragma unroll
        for (int r = 0; r < 4; r++) {
            int y = ty4 + r * 8;
            tile[y][tx] = R[(by + y) * NN + bx + tx];
        }
        __syncthreads();
#pragma unroll
        for (int r = 0; r < 4; r++) {
            int y = ty4 + r * 8;
            g_Rt[(bx + y) * NN + (by + tx)] = tile[tx][y];
        }
    } else {
        int i = (blk - TR_BLOCKS) * 256 + threadIdx.x;   // float4 index into W
        float4 v = ((const float4*)W)[i];
        ushort4 o;
        o.x = __half_as_ushort(__float2half_rn(v.x));
        o.y = __half_as_ushort(__float2half_rn(v.y));
        o.z = __half_as_ushort(__float2half_rn(v.z));
        o.w = __half_as_ushort(__float2half_rn(v.w));
        ((ushort4*)g_wh)[i] = o;
    }
}

// ---------------------------------------------------------------------------
// convert_x: x -> f16
// ---------------------------------------------------------------------------
__global__ __launch_bounds__(256) void convert_x(const float* __restrict__ src) {
    int i = blockIdx.x * 256 + threadIdx.x;
    float4 v = ((const float4*)src)[i];
    ushort4 o;
    o.x = __half_as_ushort(__float2half_rn(v.x));
    o.y = __half_as_ushort(__float2half_rn(v.y));
    o.z = __half_as_ushort(__float2half_rn(v.z));
    o.w = __half_as_ushort(__float2half_rn(v.w));
    ((ushort4*)g_xh)[i] = o;
}

// ---------------------------------------------------------------------------
// f16 1-pass GEMM via mma.sync: curh = f16(Xh*Wh + bias).
// CTA 128x64 tile, 4 warps (2m x 2n), warp tile 64x32, BK=64, 3 stages.
// Stage (24KB): 192 rows x 128B; rows 0-127 = A(xh), 128-191 = Wh.
// ---------------------------------------------------------------------------
#define BK       64
#define NCHUNK   (NI / BK)       // 8
#define NSTAGE   3
#define STAGE_B  (192 * 128)     // 24576
#define GEMM_SMEM (NSTAGE * STAGE_B)   // 73728

__global__ __launch_bounds__(128, 3) void gemm_tc(const float* __restrict__ bias) {
    extern __shared__ char smem[];
    uint32_t sb = smem_to_u32(smem);
    const int tid = threadIdx.x, lane = tid & 31, wid = tid >> 5;
    const int m0 = blockIdx.y * 128, n0 = blockIdx.x * 64;
    const int wm = (wid & 1) * 64;
    const int wn = (wid >> 1) * 32;

    float acc[4][4][4];
#pragma unroll
    for (int i = 0; i < 4; i++)
#pragma unroll
        for (int j = 0; j < 4; j++)
#pragma unroll
            for (int k = 0; k < 4; k++) acc[i][j][k] = 0.f;

    const __half* pA = g_xh + (size_t)(m0 + tid) * NI;
    const bool hasB = (tid < 64);
    const __half* pB = g_wh + (size_t)(n0 + (tid & 63)) * NI;
    const uint32_t rowA = (uint32_t)tid * 128;
    const uint32_t rowB = (uint32_t)(128 + tid) * 128;

    auto load_chunk = [&](int c) {
        uint32_t base = sb + (uint32_t)(c % NSTAGE) * STAGE_B;
#pragma unroll
        for (int j = 0; j < 8; j++)
            cp_async16(base + SWZ(rowA + j * 16), pA + c * BK + j * 8);
        if (hasB) {
#pragma unroll
            for (int j = 0; j < 8; j++)
                cp_async16(base + SWZ(rowB + j * 16), pB + c * BK + j * 8);
        }
        asm volatile("cp.async.commit_group;" ::: "memory");
    };

    const int a_row = wm + (lane & 15);
    const int a_cb  = (lane >> 4) * 16;
    const int b_row = 128 + wn + (lane & 7) + ((lane >> 4) * 8);
    const int b_cb  = ((lane >> 3) & 1) * 16;

    load_chunk(0);
    load_chunk(1);

    for (int c = 0; c < NCHUNK; c++) {
        asm volatile("cp.async.wait_group %0;" :: "n"(NSTAGE - 2) : "memory");
        __syncthreads();

        if (c + NSTAGE - 1 < NCHUNK) {
            load_chunk(c + NSTAGE - 1);
        } else {
            asm volatile("cp.async.commit_group;" ::: "memory");
        }

        uint32_t base = sb + (uint32_t)(c % NSTAGE) * STAGE_B;
#pragma unroll
        for (int kk = 0; kk < 4; kk++) {   // 4 x k16 within BK=64
            uint32_t ah[4][4], bh[4][2];
#pragma unroll
            for (int mt = 0; mt < 4; mt++) {
                uint32_t off = (uint32_t)((a_row + mt * 16) * 128 + kk * 32 + a_cb);
                ldsm_x4(ah[mt], base + SWZ(off));
            }
#pragma unroll
            for (int p = 0; p < 2; p++) {
                uint32_t off = (uint32_t)((b_row + p * 16) * 128 + kk * 32 + b_cb);
                uint32_t t4[4];
                ldsm_x4(t4, base + SWZ(off));
                bh[2 * p][0] = t4[0]; bh[2 * p][1] = t4[1];
                bh[2 * p + 1][0] = t4[2]; bh[2 * p + 1][1] = t4[3];
            }
#pragma unroll
            for (int mt = 0; mt < 4; mt++)
#pragma unroll
                for (int nt = 0; nt < 4; nt++)
                    mma16816f(acc[mt][nt], ah[mt], bh[nt]);
        }
    }

    // Epilogue: +bias, convert to f16, store half2 (4B) per fragment pair
    const int erow = m0 + wm + (lane >> 2);
    const int ecol0 = n0 + wn + (lane & 3) * 2;
    float2 brg[4];
#pragma unroll
    for (int nt = 0; nt < 4; nt++)
        brg[nt] = *(const float2*)(bias + ecol0 + nt * 8);
#pragma unroll
    for (int mt = 0; mt < 4; mt++) {
        int r0 = erow + mt * 16;
#pragma unroll
        for (int nt = 0; nt < 4; nt++) {
            __half2 h0 = __floats2half2_rn(acc[mt][nt][0] + brg[nt].x,
                                           acc[mt][nt][1] + brg[nt].y);
            __half2 h1 = __floats2half2_rn(acc[mt][nt][2] + brg[nt].x,
                                           acc[mt][nt][3] + brg[nt].y);
            *(__half2*)(g_curh + (size_t)r0 * NN + ecol0 + nt * 8) = h0;
            *(__half2*)(g_curh + (size_t)(r0 + 8) * NN + ecol0 + nt * 8) = h1;
        }
    }
}

// ---------------------------------------------------------------------------
// ALIF scan with speculation; cur stream loaded as f16 (uint2 = 4 halves),
// all state math in fp32. 2 CTAs per batch split the output streams.
// ---------------------------------------------------------------------------
__device__ __forceinline__ float4 cvt_cur(uint2 cr) {
    float2 c01 = __half22float2(*(__half2*)&cr.x);
    float2 c23 = __half22float2(*(__half2*)&cr.y);
    float4 c; c.x = c01.x; c.y = c01.y; c.z = c23.x; c.w = c23.y;
    return c;
}

__global__ __launch_bounds__(128) void alif_scan(const float* __restrict__ beta,
                                                 const float* __restrict__ beta2,
                                                 const float* __restrict__ decay_v,
                                                 const float* __restrict__ decay_b,
                                                 float* __restrict__ out) {
    const int b = blockIdx.x >> 1;
    const int p = blockIdx.x & 1;
    const int tid = threadIdx.x;
    const int w = tid >> 5, lane = tid & 31;

    __shared__ int wsum[4];
    __shared__ int act[NN];

    const float4 be = ((const float4*)beta)[tid];
    const float4 b2 = ((const float4*)beta2)[tid];
    const float4 dv = ((const float4*)decay_v)[tid];
    const float4 db = ((const float4*)decay_b)[tid];
    const float4 omdv = {1.f - dv.x, 1.f - dv.y, 1.f - dv.z, 1.f - dv.w};
    const float4 omdb = {1.f - db.x, 1.f - db.y, 1.f - db.z, 1.f - db.w};

    float4 v  = {0.f, 0.f, 0.f, 0.f};
    float4 bb = {0.f, 0.f, 0.f, 0.f};
    float4 zp = {0.f, 0.f, 0.f, 0.f};
    int nact = 0;

    const uint2* cur2 = (const uint2*)(g_curh + (size_t)b * NT * NN);
    const float4* Rt4 = (const float4*)g_Rt;

    float* zsb = out + (size_t)b * NT * NN;
    float* vf  = out + ZS_ELEMS + (size_t)(0 * NB + b) * ST_STRIDE;
    float* zf  = out + ZS_ELEMS + (size_t)(1 * NB + b) * ST_STRIDE;
    float* bf  = out + ZS_ELEMS + (size_t)(2 * NB + b) * ST_STRIDE;

    const float4 zero4 = {0.f, 0.f, 0.f, 0.f};
    if (p == 0) {
        ((float4*)vf)[tid] = zero4;
    } else {
        ((float4*)zf)[tid] = zero4;
        ((float4*)bf)[tid] = zero4;
    }

    uint2 cpre[8];
#pragma unroll
    for (int i = 0; i < 8; i++) cpre[i] = cur2[(size_t)i * 128 + tid];

    auto slow_window = [&](int tb) {
        for (int u = 0; u < 8; u++) {
            const int t = tb + u;
            float4 c = cvt_cur(cur2[(size_t)t * 128 + tid]);

            float4 rec = {0.f, 0.f, 0.f, 0.f};
            for (int k = 0; k < nact; k++) {
                float4 r = Rt4[(size_t)act[k] * 128 + tid];
                rec.x += r.x; rec.y += r.y; rec.z += r.z; rec.w += r.w;
            }

            v.x *= (1.f - zp.x); v.y *= (1.f - zp.y); v.z *= (1.f - zp.z); v.w *= (1.f - zp.w);
            float4 vt;
            vt.x = dv.x * v.x + omdv.x * ((c.x + rec.x) - bb.x);
            vt.y = dv.y * v.y + omdv.y * ((c.y + rec.y) - bb.y);
            vt.z = dv.z * v.z + omdv.z * ((c.z + rec.z) - bb.z);
            vt.w = dv.w * v.w + omdv.w * ((c.w + rec.w) - bb.w);
            float4 zt;
            zt.x = (vt.x >= 1.0f) ? 1.f : 0.f;
            zt.y = (vt.y >= 1.0f) ? 1.f : 0.f;
            zt.z = (vt.z >= 1.0f) ? 1.f : 0.f;
            zt.w = (vt.w >= 1.0f) ? 1.f : 0.f;
            bb.x = db.x * bb.x + omdb.x * (be.x * vt.x + b2.x * zt.x);
            bb.y = db.y * bb.y + omdb.y * (be.y * vt.y + b2.y * zt.y);
            bb.z = db.z * bb.z + omdb.z * (be.z * vt.z + b2.z * zt.z);
            bb.w = db.w * bb.w + omdb.w * (be.w * vt.w + b2.w * zt.w);
            v = vt; zp = zt;

            size_t tpo = (size_t)(t + 1) * 128 + tid;
            if (p == 0) {
                ((float4*)zsb)[(size_t)t * 128 + tid] = zt;
                ((float4*)vf)[tpo] = vt;
            } else {
                ((float4*)zf)[tpo] = zt;
                ((float4*)bf)[tpo] = bb;
            }

            int any = (zt.x != 0.f) | (zt.y != 0.f) | (zt.z != 0.f) | (zt.w != 0.f);
            int flag = __syncthreads_count(any);
            if (flag) {
                int myspk = (zt.x != 0.f) + (zt.y != 0.f) + (zt.z != 0.f) + (zt.w != 0.f);
                int incl = myspk;
#pragma unroll
                for (int d = 1; d < 32; d <<= 1) {
                    int n = __shfl_up_sync(0xffffffffu, incl, d);
                    if (lane >= d) incl += n;
                }
                if (lane == 31) wsum[w] = incl;
                __syncthreads();
                int basep = 0, tot = 0;
#pragma unroll
                for (int i = 0; i < 4; i++) {
                    int sv = wsum[i];
                    if (i < w) basep += sv;
                    tot += sv;
                }
                int pos = basep + incl - myspk;
                int o0 = tid * 4;
                if (zt.x != 0.f) act[pos++] = o0 + 0;
                if (zt.y != 0.f) act[pos++] = o0 + 1;
                if (zt.z != 0.f) act[pos++] = o0 + 2;
                if (zt.w != 0.f) act[pos++] = o0 + 3;
                __syncthreads();
                nact = tot;
            } else {
                nact = 0;
            }
        }
#pragma unroll
        for (int u = 0; u < 8; u++) {
            int tp = tb + 8 + u;
            if (tp < NT) cpre[u] = cur2[(size_t)tp * 128 + tid];
        }
    };

    for (int tb = 0; tb < NT; tb += 8) {
        if (nact == 0) {
            const float4 v0 = v, bb0 = bb;
            int spec = 0;
#pragma unroll
            for (int u = 0; u < 8; u++) {
                const int t = tb + u;
                float4 c = cvt_cur(cpre[u]);
                if (t + 8 < NT) cpre[u] = cur2[(size_t)(t + 8) * 128 + tid];

                float4 vt;
                vt.x = dv.x * v.x + omdv.x * (c.x - bb.x);
                vt.y = dv.y * v.y + omdv.y * (c.y - bb.y);
                vt.z = dv.z * v.z + omdv.z * (c.z - bb.z);
                vt.w = dv.w * v.w + omdv.w * (c.w - bb.w);
                float4 zt;
                zt.x = (vt.x >= 1.0f) ? 1.f : 0.f;
                zt.y = (vt.y >= 1.0f) ? 1.f : 0.f;
                zt.z = (vt.z >= 1.0f) ? 1.f : 0.f;
                zt.w = (vt.w >= 1.0f) ? 1.f : 0.f;
                spec |= (zt.x != 0.f) | (zt.y != 0.f) | (zt.z != 0.f) | (zt.w != 0.f);
                bb.x = db.x * bb.x + omdb.x * (be.x * vt.x + b2.x * zt.x);
                bb.y = db.y * bb.y + omdb.y * (be.y * vt.y + b2.y * zt.y);
                bb.z = db.z * bb.z + omdb.z * (be.z * vt.z + b2.z * zt.z);
                bb.w = db.w * bb.w + omdb.w * (be.w * vt.w + b2.w * zt.w);
                v = vt;

                size_t tpo = (size_t)(t + 1) * 128 + tid;
                if (p == 0) {
                    ((float4*)zsb)[(size_t)t * 128 + tid] = zt;
                    ((float4*)vf)[tpo] = vt;
                } else {
                    ((float4*)zf)[tpo] = zt;
                    ((float4*)bf)[tpo] = bb;
                }
            }
            int flag = __syncthreads_count(spec);
            if (flag) {
                v = v0; bb = bb0; zp = zero4; nact = 0;
                slow_window(tb);
            } else {
                zp = zero4; nact = 0;
            }
        } else {
            slow_window(tb);
        }
    }
}

// ---------------------------------------------------------------------------
extern "C" void kernel_launch(void* const* d_in, const int* in_sizes, int n_in,
                              void* d_out, int out_size) {
    const float* x     = (const float*)d_in[0];
    const float* W     = (const float*)d_in[1];
    const float* bias  = (const float*)d_in[2];
    const float* R     = (const float*)d_in[3];
    const float* beta  = (const float*)d_in[4];
    const float* beta2 = (const float*)d_in[5];
    const float* dvp   = (const float*)d_in[6];
    const float* dbp   = (const float*)d_in[7];
    float* out = (float*)d_out;

    cudaFuncSetAttribute(gemm_tc, cudaFuncAttributeMaxDynamicSharedMemorySize, GEMM_SMEM);

    prep_w<<<TR_BLOCKS + (NN * NI / 4) / 256, 256>>>(R, W);
    convert_x<<<(NM * NI / 4) / 256, 256>>>(x);

    dim3 ggrid(NN / 64, NM / 128);   // (8, 500), n fastest
    gemm_tc<<<ggrid, 128, GEMM_SMEM>>>(bias);

    alif_scan<<<2 * NB, 128>>>(beta, beta2, dvp, dbp, out);
}

// round 10
// speedup vs baseline: 4.5145x; 1.0339x over previous
#include <cuda_runtime.h>
#include <cuda_bf16.h>
#include <cuda_fp16.h>
#include <cstdint>

// Problem constants
#define NB   64
#define NT   1000
#define NN   512
#define NI   512
#define NM   (NB*NT)

#define ZS_ELEMS   (NB*NT*NN)
#define ST_STRIDE  ((NT+1)*NN)

// ---------------------------------------------------------------------------
// Scratch (device globals — no allocation allowed)
// ---------------------------------------------------------------------------
__device__ __align__(16) __half g_curh[(size_t)NM * NN];   // cur in f16
__device__ float  g_Rt[NN * NN];
__device__ __align__(16) __half g_xh[(size_t)NM * NI];
__device__ __align__(16) __half g_wh[NN * NI];

// ---------------------------------------------------------------------------
// Portable PTX helpers (sm_80+ only — tcgen05 unavailable at compute_103)
// ---------------------------------------------------------------------------
__device__ __forceinline__ uint32_t smem_to_u32(const void* p) {
    uint32_t a;
    asm("{ .reg .u64 t; cvta.to.shared.u64 t, %1; cvt.u32.u64 %0, t; }" : "=r"(a) : "l"(p));
    return a;
}
__device__ __forceinline__ void cp_async16(uint32_t dst, const void* src) {
    asm volatile("cp.async.cg.shared.global [%0], [%1], 16;" :: "r"(dst), "l"(src) : "memory");
}
__device__ __forceinline__ void ldsm_x4(uint32_t r[4], uint32_t addr) {
    asm volatile("ldmatrix.sync.aligned.m8n8.x4.shared.b16 {%0,%1,%2,%3}, [%4];"
        : "=r"(r[0]), "=r"(r[1]), "=r"(r[2]), "=r"(r[3]) : "r"(addr));
}
__device__ __forceinline__ void mma16816f(float d[4], const uint32_t a[4], const uint32_t b[2]) {
    asm volatile("mma.sync.aligned.m16n8k16.row.col.f32.f16.f16.f32 "
        "{%0,%1,%2,%3}, {%4,%5,%6,%7}, {%8,%9}, {%0,%1,%2,%3};"
        : "+f"(d[0]), "+f"(d[1]), "+f"(d[2]), "+f"(d[3])
        : "r"(a[0]), "r"(a[1]), "r"(a[2]), "r"(a[3]), "r"(b[0]), "r"(b[1]));
}
#define SWZ(off) ((off) ^ (((off) >> 3) & 0x70))

// ---------------------------------------------------------------------------
// prep_all: one launch for all preprocessing.
//   blocks [0, 256):        transpose R -> g_Rt (32x32 tile each)
//   blocks [256, 512):      convert W -> f16 g_wh
//   blocks [512, 512+32768): convert x -> f16 g_xh
// ---------------------------------------------------------------------------
#define TR_BLOCKS 256                    // (NN/32)^2
#define W_BLOCKS  ((NN * NI / 4) / 256)  // 256
#define X_BLOCKS  ((NM * NI / 4) / 256)  // 32768
__global__ __launch_bounds__(256) void prep_all(const float* __restrict__ R,
                                                const float* __restrict__ W,
                                                const float* __restrict__ x) {
    int blk = blockIdx.x;
    if (blk < TR_BLOCKS) {
        __shared__ float tile[32][33];
        int bx = (blk & 15) * 32, by = (blk >> 4) * 32;
        int tx = threadIdx.x & 31, ty8 = threadIdx.x >> 5;
#pragma unroll
        for (int r = 0; r < 4; r++) {
            int y = ty8 + r * 8;
            tile[y][tx] = R[(by + y) * NN + bx + tx];
        }
        __syncthreads();
#pragma unroll
        for (int r = 0; r < 4; r++) {
            int y = ty8 + r * 8;
            g_Rt[(bx + y) * NN + (by + tx)] = tile[tx][y];
        }
    } else if (blk < TR_BLOCKS + W_BLOCKS) {
        int i = (blk - TR_BLOCKS) * 256 + threadIdx.x;
        float4 v = ((const float4*)W)[i];
        ushort4 o;
        o.x = __half_as_ushort(__float2half_rn(v.x));
        o.y = __half_as_ushort(__float2half_rn(v.y));
        o.z = __half_as_ushort(__float2half_rn(v.z));
        o.w = __half_as_ushort(__float2half_rn(v.w));
        ((ushort4*)g_wh)[i] = o;
    } else {
        int i = (blk - TR_BLOCKS - W_BLOCKS) * 256 + threadIdx.x;
        float4 v = ((const float4*)x)[i];
        ushort4 o;
        o.x = __half_as_ushort(__float2half_rn(v.x));
        o.y = __half_as_ushort(__float2half_rn(v.y));
        o.z = __half_as_ushort(__float2half_rn(v.z));
        o.w = __half_as_ushort(__float2half_rn(v.w));
        ((ushort4*)g_xh)[i] = o;
    }
}

// ---------------------------------------------------------------------------
// f16 1-pass GEMM via mma.sync: curh = f16(Xh*Wh + bias).
// CTA 128x64 tile, 4 warps (2m x 2n), warp tile 64x32, BK=64, 3 stages.
// ---------------------------------------------------------------------------
#define BK       64
#define NCHUNK   (NI / BK)       // 8
#define NSTAGE   3
#define STAGE_B  (192 * 128)     // 24576
#define GEMM_SMEM (NSTAGE * STAGE_B)   // 73728

__global__ __launch_bounds__(128, 3) void gemm_tc(const float* __restrict__ bias) {
    extern __shared__ char smem[];
    uint32_t sb = smem_to_u32(smem);
    const int tid = threadIdx.x, lane = tid & 31, wid = tid >> 5;
    const int m0 = blockIdx.y * 128, n0 = blockIdx.x * 64;
    const int wm = (wid & 1) * 64;
    const int wn = (wid >> 1) * 32;

    float acc[4][4][4];
#pragma unroll
    for (int i = 0; i < 4; i++)
#pragma unroll
        for (int j = 0; j < 4; j++)
#pragma unroll
            for (int k = 0; k < 4; k++) acc[i][j][k] = 0.f;

    const __half* pA = g_xh + (size_t)(m0 + tid) * NI;
    const bool hasB = (tid < 64);
    const __half* pB = g_wh + (size_t)(n0 + (tid & 63)) * NI;
    const uint32_t rowA = (uint32_t)tid * 128;
    const uint32_t rowB = (uint32_t)(128 + tid) * 128;

    auto load_chunk = [&](int c) {
        uint32_t base = sb + (uint32_t)(c % NSTAGE) * STAGE_B;
#pragma unroll
        for (int j = 0; j < 8; j++)
            cp_async16(base + SWZ(rowA + j * 16), pA + c * BK + j * 8);
        if (hasB) {
#pragma unroll
            for (int j = 0; j < 8; j++)
                cp_async16(base + SWZ(rowB + j * 16), pB + c * BK + j * 8);
        }
        asm volatile("cp.async.commit_group;" ::: "memory");
    };

    const int a_row = wm + (lane & 15);
    const int a_cb  = (lane >> 4) * 16;
    const int b_row = 128 + wn + (lane & 7) + ((lane >> 4) * 8);
    const int b_cb  = ((lane >> 3) & 1) * 16;

    load_chunk(0);
    load_chunk(1);

    for (int c = 0; c < NCHUNK; c++) {
        asm volatile("cp.async.wait_group %0;" :: "n"(NSTAGE - 2) : "memory");
        __syncthreads();

        if (c + NSTAGE - 1 < NCHUNK) {
            load_chunk(c + NSTAGE - 1);
        } else {
            asm volatile("cp.async.commit_group;" ::: "memory");
        }

        uint32_t base = sb + (uint32_t)(c % NSTAGE) * STAGE_B;
#pragma unroll
        for (int kk = 0; kk < 4; kk++) {
            uint32_t ah[4][4], bh[4][2];
#pragma unroll
            for (int mt = 0; mt < 4; mt++) {
                uint32_t off = (uint32_t)((a_row + mt * 16) * 128 + kk * 32 + a_cb);
                ldsm_x4(ah[mt], base + SWZ(off));
            }
#pragma unroll
            for (int p = 0; p < 2; p++) {
                uint32_t off = (uint32_t)((b_row + p * 16) * 128 + kk * 32 + b_cb);
                uint32_t t4[4];
                ldsm_x4(t4, base + SWZ(off));
                bh[2 * p][0] = t4[0]; bh[2 * p][1] = t4[1];
                bh[2 * p + 1][0] = t4[2]; bh[2 * p + 1][1] = t4[3];
            }
#pragma unroll
            for (int mt = 0; mt < 4; mt++)
#pragma unroll
                for (int nt = 0; nt < 4; nt++)
                    mma16816f(acc[mt][nt], ah[mt], bh[nt]);
        }
    }

    const int erow = m0 + wm + (lane >> 2);
    const int ecol0 = n0 + wn + (lane & 3) * 2;
    float2 brg[4];
#pragma unroll
    for (int nt = 0; nt < 4; nt++)
        brg[nt] = *(const float2*)(bias + ecol0 + nt * 8);
#pragma unroll
    for (int mt = 0; mt < 4; mt++) {
        int r0 = erow + mt * 16;
#pragma unroll
        for (int nt = 0; nt < 4; nt++) {
            __half2 h0 = __floats2half2_rn(acc[mt][nt][0] + brg[nt].x,
                                           acc[mt][nt][1] + brg[nt].y);
            __half2 h1 = __floats2half2_rn(acc[mt][nt][2] + brg[nt].x,
                                           acc[mt][nt][3] + brg[nt].y);
            *(__half2*)(g_curh + (size_t)r0 * NN + ecol0 + nt * 8) = h0;
            *(__half2*)(g_curh + (size_t)(r0 + 8) * NN + ecol0 + nt * 8) = h1;
        }
    }
}

// ---------------------------------------------------------------------------
// ALIF scan: 128 CTAs (2 per batch, stream-split), 512 threads, 1 neuron
// per thread -> 16 warps/SM of latency cover. Speculative 8-step windows
// (one __syncthreads_count each); full ballot path on spikes.
// ---------------------------------------------------------------------------
__global__ __launch_bounds__(512) void alif_scan(const float* __restrict__ beta,
                                                 const float* __restrict__ beta2,
                                                 const float* __restrict__ decay_v,
                                                 const float* __restrict__ decay_b,
                                                 float* __restrict__ out) {
    const int b = blockIdx.x >> 1;
    const int p = blockIdx.x & 1;
    const int tid = threadIdx.x;
    const int w = tid >> 5, lane = tid & 31;

    __shared__ uint32_t zmask[16];
    __shared__ int act[NN];

    const float be = beta[tid];
    const float b2 = beta2[tid];
    const float dv = decay_v[tid];
    const float db = decay_b[tid];
    const float omdv = 1.f - dv;
    const float omdb = 1.f - db;

    float v = 0.f, bb = 0.f, zp = 0.f;
    int nact = 0;

    const __half* cur = g_curh + (size_t)b * NT * NN + tid;
    const float*  Rto = g_Rt + tid;

    float* zsb = out + (size_t)b * NT * NN + tid;
    float* vf  = out + ZS_ELEMS + (size_t)(0 * NB + b) * ST_STRIDE + tid;
    float* zf  = out + ZS_ELEMS + (size_t)(1 * NB + b) * ST_STRIDE + tid;
    float* bf  = out + ZS_ELEMS + (size_t)(2 * NB + b) * ST_STRIDE + tid;

    if (p == 0) {
        vf[0] = 0.f;
    } else {
        zf[0] = 0.f;
        bf[0] = 0.f;
    }

    __half cpre[8];
#pragma unroll
    for (int i = 0; i < 8; i++) cpre[i] = cur[(size_t)i * NN];

    // Full-accuracy window: per-step sync + spike compaction. Reloads c from
    // global; refills the prefetch ring afterwards.
    auto slow_window = [&](int tb) {
        for (int u = 0; u < 8; u++) {
            const int t = tb + u;
            float c = __half2float(cur[(size_t)t * NN]);

            float rec = 0.f;
            for (int k = 0; k < nact; k++) rec += Rto[(size_t)act[k] * NN];

            v *= (1.f - zp);
            float vt = dv * v + omdv * ((c + rec) - bb);
            float zt = (vt >= 1.0f) ? 1.f : 0.f;
            bb = db * bb + omdb * (be * vt + b2 * zt);
            v = vt; zp = zt;

            size_t tpo = (size_t)(t + 1) * NN;
            if (p == 0) {
                zsb[(size_t)t * NN] = zt;
                vf[tpo] = vt;
            } else {
                zf[tpo] = zt;
                bf[tpo] = bb;
            }

            uint32_t m = __ballot_sync(0xffffffffu, zt != 0.f);
            if (lane == 0) zmask[w] = m;
            __syncthreads();
            int myoff = 0, tot = 0;
#pragma unroll
            for (int i = 0; i < 16; i++) {
                int pc = __popc(zmask[i]);
                if (i < w) myoff += pc;
                tot += pc;
            }
            if (zt != 0.f) {
                int rank = __popc(m & ((1u << lane) - 1u));
                act[myoff + rank] = tid;
            }
            nact = tot;
            __syncthreads();
        }
#pragma unroll
        for (int u = 0; u < 8; u++) {
            int tp = tb + 8 + u;
            if (tp < NT) cpre[u] = cur[(size_t)tp * NN];
        }
    };

    for (int tb = 0; tb < NT; tb += 8) {
        if (nact == 0) {
            const float v0 = v, bb0 = bb;
            int spec = 0;
#pragma unroll
            for (int u = 0; u < 8; u++) {
                const int t = tb + u;
                float c = __half2float(cpre[u]);
                if (t + 8 < NT) cpre[u] = cur[(size_t)(t + 8) * NN];

                float vt = dv * v + omdv * (c - bb);
                float zt = (vt >= 1.0f) ? 1.f : 0.f;
                spec |= (zt != 0.f);
                bb = db * bb + omdb * (be * vt + b2 * zt);
                v = vt;

                size_t tpo = (size_t)(t + 1) * NN;
                if (p == 0) {
                    zsb[(size_t)t * NN] = zt;
                    vf[tpo] = vt;
                } else {
                    zf[tpo] = zt;
                    bf[tpo] = bb;
                }
            }
            int flag = __syncthreads_count(spec);
            if (flag) {
                v = v0; bb = bb0; zp = 0.f; nact = 0;
                slow_window(tb);
            } else {
                zp = 0.f; nact = 0;
            }
        } else {
            slow_window(tb);
        }
    }
}

// ---------------------------------------------------------------------------
extern "C" void kernel_launch(void* const* d_in, const int* in_sizes, int n_in,
                              void* d_out, int out_size) {
    const float* x     = (const float*)d_in[0];
    const float* W     = (const float*)d_in[1];
    const float* bias  = (const float*)d_in[2];
    const float* R     = (const float*)d_in[3];
    const float* beta  = (const float*)d_in[4];
    const float* beta2 = (const float*)d_in[5];
    const float* dvp   = (const float*)d_in[6];
    const float* dbp   = (const float*)d_in[7];
    float* out = (float*)d_out;

    cudaFuncSetAttribute(gemm_tc, cudaFuncAttributeMaxDynamicSharedMemorySize, GEMM_SMEM);

    prep_all<<<TR_BLOCKS + W_BLOCKS + X_BLOCKS, 256>>>(R, W, x);

    dim3 ggrid(NN / 64, NM / 128);   // (8, 500), n fastest
    gemm_tc<<<ggrid, 128, GEMM_SMEM>>>(bias);

    alif_scan<<<2 * NB, 512>>>(beta, beta2, dvp, dbp, out);
}